// round 7
// baseline (speedup 1.0000x reference)
#include <cuda_runtime.h>
#include <cuda_bf16.h>
#include <stdint.h>

// ---------------------------------------------------------------------------
// Problem constants
// ---------------------------------------------------------------------------
#define D_DIM 768
#define S_LEN 4096
#define B_BATCH 4
#define M_TOT (B_BATCH * S_LEN)            // 16384
#define BSD (B_BATCH * S_LEN * D_DIM)
#define SSLL ((long long)S_LEN * S_LEN)
#define ATT_N ((size_t)B_BATCH * S_LEN * S_LEN)
#define DD (D_DIM * D_DIM)

// ---------------------------------------------------------------------------
// Static device scratch (bf16 hi/lo split operand storage + fp32 intermediates)
// ---------------------------------------------------------------------------
__device__ __align__(256) float g_att[ATT_N];                      // 256 MB
__device__ __align__(256) __nv_bfloat16 g_attH[ATT_N];             // 134 MB
__device__ __align__(256) __nv_bfloat16 g_attL[ATT_N];             // 134 MB
__device__ __align__(256) __nv_bfloat16 g_xH[BSD], g_xL[BSD];
__device__ __align__(256) __nv_bfloat16 g_QH[BSD], g_QL[BSD];
__device__ __align__(256) __nv_bfloat16 g_KH[BSD], g_KL[BSD];
__device__ __align__(256) float g_V[BSD];
__device__ __align__(256) float g_Y[BSD];
__device__ __align__(256) __nv_bfloat16 g_VtH[BSD], g_VtL[BSD];
__device__ __align__(256) __nv_bfloat16 g_YpH[BSD], g_YpL[BSD];
__device__ __align__(256) __nv_bfloat16 g_WqH[DD], g_WqL[DD];
__device__ __align__(256) __nv_bfloat16 g_WkH[DD], g_WkL[DD];
__device__ __align__(256) __nv_bfloat16 g_WvH[DD], g_WvL[DD];
__device__ __align__(256) __nv_bfloat16 g_WcH[DD], g_WcL[DD];

// ---------------------------------------------------------------------------
// helpers
// ---------------------------------------------------------------------------
__device__ __forceinline__ uint32_t smem_u32(const void* p) {
    uint32_t a;
    asm("{ .reg .u64 t; cvta.to.shared.u64 t, %1; cvt.u32.u64 %0, t; }" : "=r"(a) : "l"(p));
    return a;
}
__device__ __forceinline__ void ldmx4(uint32_t addr, uint32_t* r) {
    asm volatile("ldmatrix.sync.aligned.m8n8.x4.shared.b16 {%0,%1,%2,%3}, [%4];"
                 : "=r"(r[0]), "=r"(r[1]), "=r"(r[2]), "=r"(r[3]) : "r"(addr));
}
__device__ __forceinline__ void mma16816(float* d, const uint32_t* a, uint32_t b0, uint32_t b1) {
    asm volatile("mma.sync.aligned.m16n8k16.row.col.f32.bf16.bf16.f32 "
                 "{%0,%1,%2,%3}, {%4,%5,%6,%7}, {%8,%9}, {%0,%1,%2,%3};"
                 : "+f"(d[0]), "+f"(d[1]), "+f"(d[2]), "+f"(d[3])
                 : "r"(a[0]), "r"(a[1]), "r"(a[2]), "r"(a[3]), "r"(b0), "r"(b1));
}
#define CP_ASYNC16(dst, src) \
    asm volatile("cp.async.cg.shared.global [%0], [%1], 16;" :: "r"(dst), "l"(src) : "memory")
#define CP_COMMIT() asm volatile("cp.async.commit_group;" ::: "memory")
#define CP_WAIT(n)  asm volatile("cp.async.wait_group %0;" :: "n"(n) : "memory")

__device__ __forceinline__ void split1(float v, __nv_bfloat16& h, __nv_bfloat16& l) {
    h = __float2bfloat16_rn(v);
    l = __float2bfloat16_rn(v - __bfloat162float(h));
}

// ---------------------------------------------------------------------------
// bf16 warp-MMA GEMM: C[M,N] = (Ah+Al)[M,K] @ (Bh+Bl)^T[N,K] + bias
// 3 MMA terms: hi*hi + hi*lo + lo*hi, fp32 register accumulation.
// Block tile 128x128, BK=64 bf16, 8 warps (2m x 4n), warp tile 64x32.
// cp.async 3-stage pipeline; 144B padded smem rows (conflict-free ldmatrix).
// SPLIT_OUT: epilogue writes bf16 hi/lo pair arrays instead of fp32 C.
// ---------------------------------------------------------------------------
#define BM 128
#define BN 128
#define BK 64
#define ROWB 144
#define MATB (128 * ROWB)          // 18432
#define OFF_AHI 0
#define OFF_ALO (1 * MATB)
#define OFF_BHI (2 * MATB)
#define OFF_BLO (3 * MATB)
#define STG (4 * MATB)             // 73728
#define NST 3
#define GSMEM (NST * STG)          // 221184

template <bool SPLIT_OUT>
__global__ void __launch_bounds__(256, 1)
gemm_mma(const __nv_bfloat16* __restrict__ Ah, const __nv_bfloat16* __restrict__ Al,
         const __nv_bfloat16* __restrict__ Bh, const __nv_bfloat16* __restrict__ Bl,
         const float* __restrict__ bias,
         float* __restrict__ C, __nv_bfloat16* __restrict__ Ch, __nv_bfloat16* __restrict__ Cl,
         int N, int K, long long sA, long long sB, long long sC)
{
    extern __shared__ char sm[];
    const uint32_t sb = smem_u32(sm);
    const int tid = threadIdx.x;
    const int wid = tid >> 5;
    const int lane = tid & 31;
    const int wm = wid >> 2;          // 0..1
    const int wn = wid & 3;           // 0..3
    const long long m0 = blockIdx.y * BM;
    const long long n0 = blockIdx.x * BN;
    const long long zA = (long long)blockIdx.z * sA;
    const long long zB = (long long)blockIdx.z * sB;
    const long long zC = (long long)blockIdx.z * sC;

    const __nv_bfloat16* srcs[4] = {
        Ah + zA + m0 * K, Al + zA + m0 * K,
        Bh + zB + n0 * K, Bl + zB + n0 * K };

    // producer chunk mapping: id = tid + 256*i -> row = id>>3, col16 = id&7
    const int pr = tid >> 3;          // base row 0..31
    const int pc = tid & 7;           // 16B chunk 0..7

    const uint32_t lmo = (uint32_t)((lane & 15) * ROWB + (lane >> 4) * 16);

    float acc[4][4][4];
    #pragma unroll
    for (int i = 0; i < 4; i++)
        #pragma unroll
        for (int j = 0; j < 4; j++)
            #pragma unroll
            for (int q = 0; q < 4; q++) acc[i][j][q] = 0.0f;

    const int KT = K / BK;

    // ---- prologue: stages 0..NST-2 ----
    #pragma unroll
    for (int s = 0; s < NST - 1; s++) {
        const uint32_t stb = sb + (uint32_t)s * STG;
        #pragma unroll
        for (int m = 0; m < 4; m++) {
            #pragma unroll
            for (int i = 0; i < 4; i++) {
                int r = pr + 32 * i;
                const __nv_bfloat16* src = srcs[m] + (long long)r * K + s * BK + pc * 8;
                uint32_t dst = stb + (uint32_t)(m * MATB + r * ROWB + pc * 16);
                CP_ASYNC16(dst, src);
            }
        }
        CP_COMMIT();
    }

    for (int kt = 0; kt < KT; kt++) {
        CP_WAIT(NST - 2);
        __syncthreads();

        // issue loads for tile kt+NST-1
        const int nx = kt + NST - 1;
        if (nx < KT) {
            const uint32_t stb = sb + (uint32_t)(nx % NST) * STG;
            #pragma unroll
            for (int m = 0; m < 4; m++) {
                #pragma unroll
                for (int i = 0; i < 4; i++) {
                    int r = pr + 32 * i;
                    const __nv_bfloat16* src = srcs[m] + (long long)r * K + nx * BK + pc * 8;
                    uint32_t dst = stb + (uint32_t)(m * MATB + r * ROWB + pc * 16);
                    CP_ASYNC16(dst, src);
                }
            }
        }
        CP_COMMIT();

        // ---- MMA on stage kt%NST ----
        const uint32_t stb = sb + (uint32_t)(kt % NST) * STG;
        #pragma unroll
        for (int ks = 0; ks < 4; ks++) {
            const uint32_t kb = (uint32_t)(ks * 32);   // 16 bf16 * 2B
            uint32_t ah[4][4], al[4][4];
            uint32_t bh[2][4], bl[2][4];
            #pragma unroll
            for (int mt = 0; mt < 4; mt++) {
                uint32_t rowb = (uint32_t)((wm * 64 + mt * 16) * ROWB);
                ldmx4(stb + OFF_AHI + rowb + lmo + kb, ah[mt]);
                ldmx4(stb + OFF_ALO + rowb + lmo + kb, al[mt]);
            }
            #pragma unroll
            for (int g = 0; g < 2; g++) {
                uint32_t rowb = (uint32_t)((wn * 32 + g * 16) * ROWB);
                ldmx4(stb + OFF_BHI + rowb + lmo + kb, bh[g]);
                ldmx4(stb + OFF_BLO + rowb + lmo + kb, bl[g]);
            }
            #pragma unroll
            for (int mt = 0; mt < 4; mt++) {
                #pragma unroll
                for (int nt = 0; nt < 4; nt++) {
                    const int g = nt >> 1, h = nt & 1;
                    mma16816(acc[mt][nt], ah[mt], bh[g][h], bh[g][h + 2]); // hi*hi
                    mma16816(acc[mt][nt], ah[mt], bl[g][h], bl[g][h + 2]); // hi*lo
                    mma16816(acc[mt][nt], al[mt], bh[g][h], bh[g][h + 2]); // lo*hi
                }
            }
        }
    }

    // ---- epilogue ----
    const long long rbase = m0 + wm * 64 + (lane >> 2);
    const long long cbase = n0 + wn * 32 + (lane & 3) * 2;
    #pragma unroll
    for (int nt = 0; nt < 4; nt++) {
        const long long c = cbase + nt * 8;
        float b0 = 0.0f, b1 = 0.0f;
        if (bias) { b0 = bias[c]; b1 = bias[c + 1]; }
        #pragma unroll
        for (int mt = 0; mt < 4; mt++) {
            const long long r = rbase + mt * 16;
            float v00 = acc[mt][nt][0] + b0, v01 = acc[mt][nt][1] + b1;
            float v10 = acc[mt][nt][2] + b0, v11 = acc[mt][nt][3] + b1;
            if (SPLIT_OUT) {
                __nv_bfloat16 h0, l0, h1, l1;
                split1(v00, h0, l0); split1(v01, h1, l1);
                *(__nv_bfloat162*)&Ch[zC + r * N + c] = __nv_bfloat162(h0, h1);
                *(__nv_bfloat162*)&Cl[zC + r * N + c] = __nv_bfloat162(l0, l1);
                split1(v10, h0, l0); split1(v11, h1, l1);
                *(__nv_bfloat162*)&Ch[zC + (r + 8) * N + c] = __nv_bfloat162(h0, h1);
                *(__nv_bfloat162*)&Cl[zC + (r + 8) * N + c] = __nv_bfloat162(l0, l1);
            } else {
                *(float2*)&C[zC + r * N + c]       = make_float2(v00, v01);
                *(float2*)&C[zC + (r + 8) * N + c] = make_float2(v10, v11);
            }
        }
    }
}

// ---------------------------------------------------------------------------
// Elementwise fp32 -> bf16 hi/lo split
// ---------------------------------------------------------------------------
__global__ void __launch_bounds__(256)
split_kernel(const float* __restrict__ src, __nv_bfloat16* __restrict__ hi,
             __nv_bfloat16* __restrict__ lo, long long n)
{
    long long i = ((long long)blockIdx.x * 256 + threadIdx.x) * 4;
    if (i >= n) return;
    float4 v = *(const float4*)(src + i);
    __nv_bfloat16 h, l;
    __nv_bfloat162 hv0, hv1, lv0, lv1;
    split1(v.x, h, l); hv0.x = h; lv0.x = l;
    split1(v.y, h, l); hv0.y = h; lv0.y = l;
    split1(v.z, h, l); hv1.x = h; lv1.x = l;
    split1(v.w, h, l); hv1.y = h; lv1.y = l;
    *(__nv_bfloat162*)(hi + i)     = hv0;
    *(__nv_bfloat162*)(hi + i + 2) = hv1;
    *(__nv_bfloat162*)(lo + i)     = lv0;
    *(__nv_bfloat162*)(lo + i + 2) = lv1;
}

// ---------------------------------------------------------------------------
// Row softmax; reads fp32 logits, writes bf16 hi/lo split probabilities.
// ---------------------------------------------------------------------------
__global__ void __launch_bounds__(256)
softmax_kernel(const float* __restrict__ att, __nv_bfloat16* __restrict__ outH,
               __nv_bfloat16* __restrict__ outL, float scale)
{
    __shared__ float buf[S_LEN];
    __shared__ float red[256];
    const long long row = blockIdx.x;
    const float* p = att + row * S_LEN;
    const int tid = threadIdx.x;

    float mx = -1e30f;
    for (int i = tid; i < S_LEN; i += 256) {
        float v = p[i] * scale;
        buf[i] = v;
        mx = fmaxf(mx, v);
    }
    red[tid] = mx;
    __syncthreads();
    for (int s = 128; s > 0; s >>= 1) {
        if (tid < s) red[tid] = fmaxf(red[tid], red[tid + s]);
        __syncthreads();
    }
    mx = red[0];
    __syncthreads();

    float sum = 0.0f;
    for (int i = tid; i < S_LEN; i += 256) {
        float e = __expf(buf[i] - mx);
        buf[i] = e;
        sum += e;
    }
    red[tid] = sum;
    __syncthreads();
    for (int s = 128; s > 0; s >>= 1) {
        if (tid < s) red[tid] += red[tid + s];
        __syncthreads();
    }
    float inv = 1.0f / red[0];

    __nv_bfloat16* oh = outH + row * S_LEN;
    __nv_bfloat16* ol = outL + row * S_LEN;
    for (int i = tid * 2; i < S_LEN; i += 512) {
        float v0 = buf[i] * inv, v1 = buf[i + 1] * inv;
        __nv_bfloat16 h0, l0, h1, l1;
        split1(v0, h0, l0); split1(v1, h1, l1);
        *(__nv_bfloat162*)(oh + i) = __nv_bfloat162(h0, h1);
        *(__nv_bfloat162*)(ol + i) = __nv_bfloat162(l0, l1);
    }
}

// ---------------------------------------------------------------------------
// Per-batch tiled transpose + split: src fp32 [R,C] -> dst bf16 hi/lo [C,R].
// ---------------------------------------------------------------------------
__global__ void __launch_bounds__(256)
transpose_split_kernel(const float* __restrict__ src, __nv_bfloat16* __restrict__ dstH,
                       __nv_bfloat16* __restrict__ dstL, int R, int C)
{
    __shared__ float t[32][33];
    const long long bofs = (long long)blockIdx.z * R * C;
    src += bofs; dstH += bofs; dstL += bofs;
    int c0 = blockIdx.x * 32, r0 = blockIdx.y * 32;
    for (int i = threadIdx.y; i < 32; i += 8)
        t[i][threadIdx.x] = src[(long long)(r0 + i) * C + c0 + threadIdx.x];
    __syncthreads();
    for (int i = threadIdx.y; i < 32; i += 8) {
        float v = t[threadIdx.x][i];
        __nv_bfloat16 h, l;
        split1(v, h, l);
        long long o = (long long)(c0 + i) * R + r0 + threadIdx.x;
        dstH[o] = h;
        dstL[o] = l;
    }
}

// ---------------------------------------------------------------------------
extern "C" void kernel_launch(void* const* d_in, const int* in_sizes, int n_in,
                              void* d_out, int out_size)
{
    const float* x  = (const float*)d_in[0];
    const float* Wq = (const float*)d_in[1];
    const float* bq = (const float*)d_in[2];
    const float* Wk = (const float*)d_in[3];
    const float* bk = (const float*)d_in[4];
    const float* Wv = (const float*)d_in[5];
    const float* bv = (const float*)d_in[6];
    const float* Wc = (const float*)d_in[7];
    const float* bc = (const float*)d_in[8];
    float* out = (float*)d_out;

    float *att, *V, *Y;
    __nv_bfloat16 *attH, *attL, *xH, *xL, *QH, *QL, *KH, *KL, *VtH, *VtL, *YpH, *YpL;
    __nv_bfloat16 *WqH, *WqL, *WkH, *WkL, *WvH, *WvL, *WcH, *WcL;
    cudaGetSymbolAddress((void**)&att,  g_att);
    cudaGetSymbolAddress((void**)&attH, g_attH);
    cudaGetSymbolAddress((void**)&attL, g_attL);
    cudaGetSymbolAddress((void**)&xH,   g_xH);
    cudaGetSymbolAddress((void**)&xL,   g_xL);
    cudaGetSymbolAddress((void**)&QH,   g_QH);
    cudaGetSymbolAddress((void**)&QL,   g_QL);
    cudaGetSymbolAddress((void**)&KH,   g_KH);
    cudaGetSymbolAddress((void**)&KL,   g_KL);
    cudaGetSymbolAddress((void**)&V,    g_V);
    cudaGetSymbolAddress((void**)&Y,    g_Y);
    cudaGetSymbolAddress((void**)&VtH,  g_VtH);
    cudaGetSymbolAddress((void**)&VtL,  g_VtL);
    cudaGetSymbolAddress((void**)&YpH,  g_YpH);
    cudaGetSymbolAddress((void**)&YpL,  g_YpL);
    cudaGetSymbolAddress((void**)&WqH,  g_WqH);
    cudaGetSymbolAddress((void**)&WqL,  g_WqL);
    cudaGetSymbolAddress((void**)&WkH,  g_WkH);
    cudaGetSymbolAddress((void**)&WkL,  g_WkL);
    cudaGetSymbolAddress((void**)&WvH,  g_WvH);
    cudaGetSymbolAddress((void**)&WvL,  g_WvL);
    cudaGetSymbolAddress((void**)&WcH,  g_WcH);
    cudaGetSymbolAddress((void**)&WcL,  g_WcL);

    cudaFuncSetAttribute(gemm_mma<false>, cudaFuncAttributeMaxDynamicSharedMemorySize, GSMEM);
    cudaFuncSetAttribute(gemm_mma<true>,  cudaFuncAttributeMaxDynamicSharedMemorySize, GSMEM);

    const float scale = 0.03608439182435161f;   // 768^-0.5
    const long long sd = (long long)S_LEN * D_DIM;
    dim3 blk(256);
    dim3 tblk(32, 8);

    // ---- operand pre-splits ----
    split_kernel<<<(BSD / 4 + 255) / 256, blk>>>(x,  xH,  xL,  BSD);
    split_kernel<<<(DD / 4 + 255) / 256, blk>>>(Wq, WqH, WqL, DD);
    split_kernel<<<(DD / 4 + 255) / 256, blk>>>(Wk, WkH, WkL, DD);
    split_kernel<<<(DD / 4 + 255) / 256, blk>>>(Wv, WvH, WvL, DD);
    split_kernel<<<(DD / 4 + 255) / 256, blk>>>(Wc, WcH, WcL, DD);

    // ---- QKV projections ----
    dim3 gp(D_DIM / BN, M_TOT / BM, 1);                  // (6,128,1)
    gemm_mma<true><<<gp, blk, GSMEM>>>(xH, xL, WqH, WqL, bq, nullptr, QH, QL,
                                       D_DIM, D_DIM, 0, 0, 0);
    gemm_mma<true><<<gp, blk, GSMEM>>>(xH, xL, WkH, WkL, bk, nullptr, KH, KL,
                                       D_DIM, D_DIM, 0, 0, 0);
    gemm_mma<false><<<gp, blk, GSMEM>>>(xH, xL, WvH, WvL, bv, V, nullptr, nullptr,
                                        D_DIM, D_DIM, 0, 0, 0);

    // ---- att[b] = Q[b] @ K[b]^T ----
    dim3 ga(S_LEN / BN, S_LEN / BM, B_BATCH);            // (32,32,4)
    gemm_mma<false><<<ga, blk, GSMEM>>>(QH, QL, KH, KL, nullptr, att, nullptr, nullptr,
                                        S_LEN, D_DIM, sd, sd, SSLL);

    // ---- softmax (scale folded), writes split bf16 probabilities ----
    softmax_kernel<<<M_TOT, blk>>>(att, attH, attL, scale);

    // ---- V^T per batch, split ----
    dim3 gt(D_DIM / 32, S_LEN / 32, B_BATCH);            // (24,128,4)
    transpose_split_kernel<<<gt, tblk>>>(V, VtH, VtL, S_LEN, D_DIM);

    // ---- Y[b] = att[b] @ Vt[b]^T ----
    dim3 gy(D_DIM / BN, S_LEN / BM, B_BATCH);            // (6,32,4)
    gemm_mma<false><<<gy, blk, GSMEM>>>(attH, attL, VtH, VtL, nullptr, Y, nullptr, nullptr,
                                        D_DIM, S_LEN, SSLL, sd, sd);

    // ---- permutation (per-batch transpose) + split ----
    transpose_split_kernel<<<gt, tblk>>>(Y, YpH, YpL, S_LEN, D_DIM);

    // ---- output projection -> d_out ----
    gemm_mma<false><<<gp, blk, GSMEM>>>(YpH, YpL, WcH, WcL, bc, out, nullptr, nullptr,
                                        D_DIM, D_DIM, 0, 0, 0);
}

// round 9
// speedup vs baseline: 1.4332x; 1.4332x over previous
#include <cuda_runtime.h>
#include <cuda_fp16.h>
#include <stdint.h>

// ---------------------------------------------------------------------------
// Problem constants
// ---------------------------------------------------------------------------
#define D_DIM 768
#define S_LEN 4096
#define B_BATCH 4
#define M_TOT (B_BATCH * S_LEN)            // 16384
#define BSD (B_BATCH * S_LEN * D_DIM)
#define SSLL ((long long)S_LEN * S_LEN)
#define ATT_N ((size_t)B_BATCH * S_LEN * S_LEN)
#define DD (D_DIM * D_DIM)

// ---------------------------------------------------------------------------
// Static device scratch
// ---------------------------------------------------------------------------
__device__ __align__(256) float g_att[ATT_N];                 // 256 MB fp32 logits
__device__ __align__(256) __half g_attH[ATT_N], g_attL[ATT_N];
__device__ __align__(256) __half g_xH[BSD], g_xL[BSD];
__device__ __align__(256) __half g_QH[BSD], g_QL[BSD];
__device__ __align__(256) __half g_KH[BSD];
__device__ __align__(256) float  g_V[BSD];
__device__ __align__(256) float  g_Y[BSD];
__device__ __align__(256) __half g_VtH[BSD];
__device__ __align__(256) __half g_YpH[BSD], g_YpL[BSD];
__device__ __align__(256) __half g_WqH[DD], g_WkH[DD];
__device__ __align__(256) __half g_WvH[DD], g_WvL[DD];
__device__ __align__(256) __half g_WcH[DD], g_WcL[DD];

// ---------------------------------------------------------------------------
// helpers
// ---------------------------------------------------------------------------
__device__ __forceinline__ uint32_t smem_u32(const void* p) {
    uint32_t a;
    asm("{ .reg .u64 t; cvta.to.shared.u64 t, %1; cvt.u32.u64 %0, t; }" : "=r"(a) : "l"(p));
    return a;
}
__device__ __forceinline__ void ldmx4(uint32_t addr, uint32_t* r) {
    asm volatile("ldmatrix.sync.aligned.m8n8.x4.shared.b16 {%0,%1,%2,%3}, [%4];"
                 : "=r"(r[0]), "=r"(r[1]), "=r"(r[2]), "=r"(r[3]) : "r"(addr));
}
__device__ __forceinline__ void mma16816(float* d, const uint32_t* a, uint32_t b0, uint32_t b1) {
    asm volatile("mma.sync.aligned.m16n8k16.row.col.f32.f16.f16.f32 "
                 "{%0,%1,%2,%3}, {%4,%5,%6,%7}, {%8,%9}, {%0,%1,%2,%3};"
                 : "+f"(d[0]), "+f"(d[1]), "+f"(d[2]), "+f"(d[3])
                 : "r"(a[0]), "r"(a[1]), "r"(a[2]), "r"(a[3]), "r"(b0), "r"(b1));
}
#define CP_ASYNC16(dst, src) \
    asm volatile("cp.async.cg.shared.global [%0], [%1], 16;" :: "r"(dst), "l"(src) : "memory")
#define CP_COMMIT() asm volatile("cp.async.commit_group;" ::: "memory")
template <int N>
__device__ __forceinline__ void cp_wait() {
    asm volatile("cp.async.wait_group %0;" :: "n"(N) : "memory");
}
__device__ __forceinline__ void split1h(float v, __half& h, __half& l) {
    h = __float2half_rn(v);
    l = __float2half_rn(v - __half2float(h));
}

// ---------------------------------------------------------------------------
// fp16 warp-MMA GEMM: C[M,N] = A[M,K] @ B^T[N,K] + bias
//   NTERMS=2: A = Ah+Al (split), B = Bh single.  products: ah*bh + al*bh
//   NTERMS=3: A = Ah+Al, B = Bh+Bl.              products: + ah*bl
// Block tile 128x256, BK=64 fp16, 8 warps (2m x 4n), warp tile 64x64.
// cp.async pipeline: 3 stages (NT2) / 2 stages (NT3). 144B padded smem rows.
// OUTM: 0 = fp32 C, 1 = split half Ch/Cl, 2 = single half Ch.
// ---------------------------------------------------------------------------
#define BM 128
#define BN 256
#define BK 64
#define ROWB 144
#define AMATB (128 * ROWB)          // 18432
#define BMATB (256 * ROWB)          // 36864
#define GSMEM 221184

template <int NTERMS>
__device__ __forceinline__ void produce_tile(
    uint32_t stb, const __half* pAh, const __half* pAl,
    const __half* pBh, const __half* pBl, long long K, int tid)
{
    const int pr = tid >> 3;          // 0..31
    const int pc = tid & 7;           // 0..7 (16B chunks across 128B row)
    const uint32_t dbase = (uint32_t)(pr * ROWB + pc * 16);
    const long long sbase = (long long)pr * K + pc * 8;
    #pragma unroll
    for (int i = 0; i < 4; i++) {     // A rows pr+32i
        uint32_t d = dbase + (uint32_t)(32 * i * ROWB);
        long long s = sbase + (long long)(32 * i) * K;
        CP_ASYNC16(stb + d,         pAh + s);
        CP_ASYNC16(stb + AMATB + d, pAl + s);
    }
    #pragma unroll
    for (int i = 0; i < 8; i++) {     // B rows pr+32i
        uint32_t d = dbase + (uint32_t)(32 * i * ROWB);
        long long s = sbase + (long long)(32 * i) * K;
        CP_ASYNC16(stb + 2 * AMATB + d, pBh + s);
        if (NTERMS == 3)
            CP_ASYNC16(stb + 2 * AMATB + BMATB + d, pBl + s);
    }
}

template <int NTERMS, int OUTM>
__global__ void __launch_bounds__(256, 1)
gemm_mma(const __half* __restrict__ Ah, const __half* __restrict__ Al,
         const __half* __restrict__ Bh, const __half* __restrict__ Bl,
         const float* __restrict__ bias,
         float* __restrict__ C, __half* __restrict__ Ch, __half* __restrict__ Cl,
         int N, int K, long long sA, long long sB, long long sC)
{
    constexpr int NST = (NTERMS == 3) ? 2 : 3;
    constexpr int STG = 2 * AMATB + (NTERMS - 1) * BMATB;

    extern __shared__ char sm[];
    const uint32_t sb = smem_u32(sm);
    const int tid = threadIdx.x;
    const int wid = tid >> 5;
    const int lane = tid & 31;
    const int wm = wid >> 2;          // 0..1
    const int wn = wid & 3;           // 0..3
    const long long m0 = blockIdx.y * BM;
    const long long n0 = blockIdx.x * BN;

    const __half* pAh = Ah + (long long)blockIdx.z * sA + m0 * K;
    const __half* pAl = Al + (long long)blockIdx.z * sA + m0 * K;
    const __half* pBh = Bh + (long long)blockIdx.z * sB + n0 * K;
    const __half* pBl = (NTERMS == 3) ? (Bl + (long long)blockIdx.z * sB + n0 * K) : nullptr;
    const long long zC = (long long)blockIdx.z * sC;

    const uint32_t lmo = (uint32_t)((lane & 15) * ROWB + (lane >> 4) * 16);

    float acc[4][8][4];
    #pragma unroll
    for (int i = 0; i < 4; i++)
        #pragma unroll
        for (int j = 0; j < 8; j++)
            #pragma unroll
            for (int q = 0; q < 4; q++) acc[i][j][q] = 0.0f;

    const int KT = K / BK;

    // prologue: stages 0..NST-2
    #pragma unroll
    for (int s = 0; s < NST - 1; s++) {
        produce_tile<NTERMS>(sb + (uint32_t)s * STG,
                             pAh + s * BK, pAl + s * BK, pBh + s * BK,
                             (NTERMS == 3) ? pBl + s * BK : nullptr, K, tid);
        CP_COMMIT();
    }

    for (int kt = 0; kt < KT; kt++) {
        cp_wait<NST - 2>();
        __syncthreads();

        const int nx = kt + NST - 1;
        if (nx < KT) {
            produce_tile<NTERMS>(sb + (uint32_t)(nx % NST) * STG,
                                 pAh + nx * BK, pAl + nx * BK, pBh + nx * BK,
                                 (NTERMS == 3) ? pBl + nx * BK : nullptr, K, tid);
        }
        CP_COMMIT();

        const uint32_t stb = sb + (uint32_t)(kt % NST) * STG;
        #pragma unroll
        for (int ks = 0; ks < 4; ks++) {
            const uint32_t kb = (uint32_t)(ks * 32);     // 16 halves * 2B
            uint32_t ah[4][4], al[4][4];
            #pragma unroll
            for (int mt = 0; mt < 4; mt++) {
                uint32_t rowb = (uint32_t)((wm * 64 + mt * 16) * ROWB);
                ldmx4(stb + rowb + lmo + kb, ah[mt]);
                ldmx4(stb + AMATB + rowb + lmo + kb, al[mt]);
            }
            #pragma unroll
            for (int g = 0; g < 4; g++) {                // 16-col groups of warp's 64
                uint32_t rowb = (uint32_t)((wn * 64 + g * 16) * ROWB);
                uint32_t bh[4];
                ldmx4(stb + 2 * AMATB + rowb + lmo + kb, bh);
                uint32_t bl[4];
                if (NTERMS == 3)
                    ldmx4(stb + 2 * AMATB + BMATB + rowb + lmo + kb, bl);
                #pragma unroll
                for (int mt = 0; mt < 4; mt++) {
                    #pragma unroll
                    for (int h = 0; h < 2; h++) {
                        const int nt = g * 2 + h;
                        mma16816(acc[mt][nt], ah[mt], bh[h], bh[h + 2]);   // hi*hi
                        mma16816(acc[mt][nt], al[mt], bh[h], bh[h + 2]);   // lo*hi
                        if (NTERMS == 3)
                            mma16816(acc[mt][nt], ah[mt], bl[h], bl[h + 2]); // hi*lo
                    }
                }
            }
        }
    }

    // epilogue
    const long long rb = m0 + wm * 64 + (lane >> 2);
    const long long cb = n0 + wn * 64 + (lane & 3) * 2;
    #pragma unroll
    for (int nt = 0; nt < 8; nt++) {
        const long long c = cb + nt * 8;
        float b0 = 0.0f, b1 = 0.0f;
        if (bias) { b0 = bias[c]; b1 = bias[c + 1]; }
        #pragma unroll
        for (int mt = 0; mt < 4; mt++) {
            const long long r = rb + mt * 16;
            float v00 = acc[mt][nt][0] + b0, v01 = acc[mt][nt][1] + b1;
            float v10 = acc[mt][nt][2] + b0, v11 = acc[mt][nt][3] + b1;
            if (OUTM == 0) {
                *(float2*)&C[zC + r * N + c]       = make_float2(v00, v01);
                *(float2*)&C[zC + (r + 8) * N + c] = make_float2(v10, v11);
            } else if (OUTM == 1) {
                __half h0, l0, h1, l1;
                split1h(v00, h0, l0); split1h(v01, h1, l1);
                *(__half2*)&Ch[zC + r * N + c] = __halves2half2(h0, h1);
                *(__half2*)&Cl[zC + r * N + c] = __halves2half2(l0, l1);
                split1h(v10, h0, l0); split1h(v11, h1, l1);
                *(__half2*)&Ch[zC + (r + 8) * N + c] = __halves2half2(h0, h1);
                *(__half2*)&Cl[zC + (r + 8) * N + c] = __halves2half2(l0, l1);
            } else {
                *(__half2*)&Ch[zC + r * N + c] =
                    __halves2half2(__float2half_rn(v00), __float2half_rn(v01));
                *(__half2*)&Ch[zC + (r + 8) * N + c] =
                    __halves2half2(__float2half_rn(v10), __float2half_rn(v11));
            }
        }
    }
}

// ---------------------------------------------------------------------------
// fp32 -> half split / round elementwise
// ---------------------------------------------------------------------------
__global__ void __launch_bounds__(256)
split_kernel(const float* __restrict__ src, __half* __restrict__ hi,
             __half* __restrict__ lo, long long n)
{
    long long i = ((long long)blockIdx.x * 256 + threadIdx.x) * 4;
    if (i >= n) return;
    float4 v = *(const float4*)(src + i);
    __half h, l;
    __half2 hv0, hv1, lv0, lv1;
    split1h(v.x, h, l); hv0.x = h; lv0.x = l;
    split1h(v.y, h, l); hv0.y = h; lv0.y = l;
    split1h(v.z, h, l); hv1.x = h; lv1.x = l;
    split1h(v.w, h, l); hv1.y = h; lv1.y = l;
    *(__half2*)(hi + i) = hv0;     *(__half2*)(hi + i + 2) = hv1;
    *(__half2*)(lo + i) = lv0;     *(__half2*)(lo + i + 2) = lv1;
}

__global__ void __launch_bounds__(256)
round_kernel(const float* __restrict__ src, __half* __restrict__ dst, long long n)
{
    long long i = ((long long)blockIdx.x * 256 + threadIdx.x) * 4;
    if (i >= n) return;
    float4 v = *(const float4*)(src + i);
    *(__half2*)(dst + i)     = __halves2half2(__float2half_rn(v.x), __float2half_rn(v.y));
    *(__half2*)(dst + i + 2) = __halves2half2(__float2half_rn(v.z), __float2half_rn(v.w));
}

// ---------------------------------------------------------------------------
// Row softmax; fp32 logits in, split-half probabilities out.
// ---------------------------------------------------------------------------
__global__ void __launch_bounds__(256)
softmax_kernel(const float* __restrict__ att, __half* __restrict__ outH,
               __half* __restrict__ outL, float scale)
{
    __shared__ float buf[S_LEN];
    __shared__ float red[256];
    const long long row = blockIdx.x;
    const float* p = att + row * S_LEN;
    const int tid = threadIdx.x;

    float mx = -1e30f;
    for (int i = tid; i < S_LEN; i += 256) {
        float v = p[i] * scale;
        buf[i] = v;
        mx = fmaxf(mx, v);
    }
    red[tid] = mx;
    __syncthreads();
    for (int s = 128; s > 0; s >>= 1) {
        if (tid < s) red[tid] = fmaxf(red[tid], red[tid + s]);
        __syncthreads();
    }
    mx = red[0];
    __syncthreads();

    float sum = 0.0f;
    for (int i = tid; i < S_LEN; i += 256) {
        float e = __expf(buf[i] - mx);
        buf[i] = e;
        sum += e;
    }
    red[tid] = sum;
    __syncthreads();
    for (int s = 128; s > 0; s >>= 1) {
        if (tid < s) red[tid] += red[tid + s];
        __syncthreads();
    }
    float inv = 1.0f / red[0];

    __half* oh = outH + row * S_LEN;
    __half* ol = outL + row * S_LEN;
    for (int i = tid * 2; i < S_LEN; i += 512) {
        float v0 = buf[i] * inv, v1 = buf[i + 1] * inv;
        __half h0, l0, h1, l1;
        split1h(v0, h0, l0); split1h(v1, h1, l1);
        *(__half2*)(oh + i) = __halves2half2(h0, h1);
        *(__half2*)(ol + i) = __halves2half2(l0, l1);
    }
}

// ---------------------------------------------------------------------------
// Per-batch tiled transpose fp32 [R,C] -> half [C,R]; single or split output.
// ---------------------------------------------------------------------------
__global__ void __launch_bounds__(256)
transpose_h_kernel(const float* __restrict__ src, __half* __restrict__ dst, int R, int C)
{
    __shared__ float t[32][33];
    const long long bofs = (long long)blockIdx.z * R * C;
    src += bofs; dst += bofs;
    int c0 = blockIdx.x * 32, r0 = blockIdx.y * 32;
    for (int i = threadIdx.y; i < 32; i += 8)
        t[i][threadIdx.x] = src[(long long)(r0 + i) * C + c0 + threadIdx.x];
    __syncthreads();
    for (int i = threadIdx.y; i < 32; i += 8)
        dst[(long long)(c0 + i) * R + r0 + threadIdx.x] = __float2half_rn(t[threadIdx.x][i]);
}

__global__ void __launch_bounds__(256)
transpose_split_kernel(const float* __restrict__ src, __half* __restrict__ dstH,
                       __half* __restrict__ dstL, int R, int C)
{
    __shared__ float t[32][33];
    const long long bofs = (long long)blockIdx.z * R * C;
    src += bofs; dstH += bofs; dstL += bofs;
    int c0 = blockIdx.x * 32, r0 = blockIdx.y * 32;
    for (int i = threadIdx.y; i < 32; i += 8)
        t[i][threadIdx.x] = src[(long long)(r0 + i) * C + c0 + threadIdx.x];
    __syncthreads();
    for (int i = threadIdx.y; i < 32; i += 8) {
        __half h, l;
        split1h(t[threadIdx.x][i], h, l);
        long long o = (long long)(c0 + i) * R + r0 + threadIdx.x;
        dstH[o] = h;
        dstL[o] = l;
    }
}

// ---------------------------------------------------------------------------
extern "C" void kernel_launch(void* const* d_in, const int* in_sizes, int n_in,
                              void* d_out, int out_size)
{
    const float* x  = (const float*)d_in[0];
    const float* Wq = (const float*)d_in[1];
    const float* bq = (const float*)d_in[2];
    const float* Wk = (const float*)d_in[3];
    const float* bk = (const float*)d_in[4];
    const float* Wv = (const float*)d_in[5];
    const float* bv = (const float*)d_in[6];
    const float* Wc = (const float*)d_in[7];
    const float* bc = (const float*)d_in[8];
    float* out = (float*)d_out;

    float *att, *V, *Y;
    __half *attH, *attL, *xH, *xL, *QH, *QL, *KH, *VtH, *YpH, *YpL;
    __half *WqH, *WkH, *WvH, *WvL, *WcH, *WcL;
    cudaGetSymbolAddress((void**)&att,  g_att);
    cudaGetSymbolAddress((void**)&attH, g_attH);
    cudaGetSymbolAddress((void**)&attL, g_attL);
    cudaGetSymbolAddress((void**)&xH,   g_xH);
    cudaGetSymbolAddress((void**)&xL,   g_xL);
    cudaGetSymbolAddress((void**)&QH,   g_QH);
    cudaGetSymbolAddress((void**)&QL,   g_QL);
    cudaGetSymbolAddress((void**)&KH,   g_KH);
    cudaGetSymbolAddress((void**)&V,    g_V);
    cudaGetSymbolAddress((void**)&Y,    g_Y);
    cudaGetSymbolAddress((void**)&VtH,  g_VtH);
    cudaGetSymbolAddress((void**)&YpH,  g_YpH);
    cudaGetSymbolAddress((void**)&YpL,  g_YpL);
    cudaGetSymbolAddress((void**)&WqH,  g_WqH);
    cudaGetSymbolAddress((void**)&WkH,  g_WkH);
    cudaGetSymbolAddress((void**)&WvH,  g_WvH);
    cudaGetSymbolAddress((void**)&WvL,  g_WvL);
    cudaGetSymbolAddress((void**)&WcH,  g_WcH);
    cudaGetSymbolAddress((void**)&WcL,  g_WcL);

    cudaFuncSetAttribute(gemm_mma<2,0>, cudaFuncAttributeMaxDynamicSharedMemorySize, GSMEM);
    cudaFuncSetAttribute(gemm_mma<2,1>, cudaFuncAttributeMaxDynamicSharedMemorySize, GSMEM);
    cudaFuncSetAttribute(gemm_mma<2,2>, cudaFuncAttributeMaxDynamicSharedMemorySize, GSMEM);
    cudaFuncSetAttribute(gemm_mma<3,0>, cudaFuncAttributeMaxDynamicSharedMemorySize, GSMEM);

    const float scale = 0.03608439182435161f;   // 768^-0.5
    const long long sd = (long long)S_LEN * D_DIM;
    dim3 blk(256);
    dim3 tblk(32, 8);

    // ---- operand prep ----
    split_kernel<<<(BSD / 4 + 255) / 256, blk>>>(x, xH, xL, BSD);
    round_kernel<<<(DD / 4 + 255) / 256, blk>>>(Wq, WqH, DD);
    round_kernel<<<(DD / 4 + 255) / 256, blk>>>(Wk, WkH, DD);
    split_kernel<<<(DD / 4 + 255) / 256, blk>>>(Wv, WvH, WvL, DD);
    split_kernel<<<(DD / 4 + 255) / 256, blk>>>(Wc, WcH, WcL, DD);

    // ---- projections ----
    dim3 gp(D_DIM / BN, M_TOT / BM, 1);                  // (3,128,1)
    gemm_mma<2,1><<<gp, blk, GSMEM>>>(xH, xL, WqH, nullptr, bq, nullptr, QH, QL,
                                      D_DIM, D_DIM, 0, 0, 0);
    gemm_mma<2,2><<<gp, blk, GSMEM>>>(xH, xL, WkH, nullptr, bk, nullptr, KH, nullptr,
                                      D_DIM, D_DIM, 0, 0, 0);
    gemm_mma<3,0><<<gp, blk, GSMEM>>>(xH, xL, WvH, WvL, bv, V, nullptr, nullptr,
                                      D_DIM, D_DIM, 0, 0, 0);

    // ---- att[b] = Q[b] @ K[b]^T ----
    dim3 ga(S_LEN / BN, S_LEN / BM, B_BATCH);            // (16,32,4)
    gemm_mma<2,0><<<ga, blk, GSMEM>>>(QH, QL, KH, nullptr, nullptr, att, nullptr, nullptr,
                                      S_LEN, D_DIM, sd, sd, SSLL);

    // ---- softmax -> split half probabilities ----
    softmax_kernel<<<M_TOT, blk>>>(att, attH, attL, scale);

    // ---- V^T per batch (single half) ----
    dim3 gt(D_DIM / 32, S_LEN / 32, B_BATCH);            // (24,128,4)
    transpose_h_kernel<<<gt, tblk>>>(V, VtH, S_LEN, D_DIM);

    // ---- Y[b] = att[b] @ Vt[b]^T ----
    dim3 gy(D_DIM / BN, S_LEN / BM, B_BATCH);            // (3,32,4)
    gemm_mma<2,0><<<gy, blk, GSMEM>>>(attH, attL, VtH, nullptr, nullptr, Y, nullptr, nullptr,
                                      D_DIM, S_LEN, SSLL, sd, sd);

    // ---- permutation (per-batch transpose) + split ----
    transpose_split_kernel<<<gt, tblk>>>(Y, YpH, YpL, S_LEN, D_DIM);

    // ---- output projection -> d_out (3-term, accurate) ----
    gemm_mma<3,0><<<gp, blk, GSMEM>>>(YpH, YpL, WcH, WcL, bc, out, nullptr, nullptr,
                                      D_DIM, D_DIM, 0, 0, 0);
}

// round 10
// speedup vs baseline: 1.7343x; 1.2101x over previous
#include <cuda_runtime.h>
#include <cuda_fp16.h>
#include <stdint.h>

// ---------------------------------------------------------------------------
// Problem constants
// ---------------------------------------------------------------------------
#define D_DIM 768
#define S_LEN 4096
#define B_BATCH 4
#define M_TOT (B_BATCH * S_LEN)            // 16384
#define BSD (B_BATCH * S_LEN * D_DIM)
#define SSLL ((long long)S_LEN * S_LEN)
#define ATT_N ((size_t)B_BATCH * S_LEN * S_LEN)
#define DD (D_DIM * D_DIM)

// ---------------------------------------------------------------------------
// Static device scratch
// ---------------------------------------------------------------------------
__device__ __align__(256) __half g_attLg[ATT_N];              // scaled fp16 logits
__device__ __align__(256) __half g_attP[ATT_N];               // fp16 probabilities
__device__ __align__(256) __half g_xH[BSD], g_xL[BSD];
__device__ __align__(256) __half g_QH[BSD], g_QL[BSD];        // Q pre-scaled by 768^-0.5
__device__ __align__(256) __half g_KH[BSD];
__device__ __align__(256) float  g_V[BSD];
__device__ __align__(256) float  g_Y[BSD];
__device__ __align__(256) __half g_VtH[BSD];
__device__ __align__(256) __half g_YpH[BSD], g_YpL[BSD];
__device__ __align__(256) __half g_WqH[DD], g_WkH[DD];
__device__ __align__(256) __half g_WvH[DD], g_WvL[DD];
__device__ __align__(256) __half g_WcH[DD], g_WcL[DD];

// ---------------------------------------------------------------------------
// helpers
// ---------------------------------------------------------------------------
__device__ __forceinline__ uint32_t smem_u32(const void* p) {
    uint32_t a;
    asm("{ .reg .u64 t; cvta.to.shared.u64 t, %1; cvt.u32.u64 %0, t; }" : "=r"(a) : "l"(p));
    return a;
}
__device__ __forceinline__ void ldmx4(uint32_t addr, uint32_t* r) {
    asm volatile("ldmatrix.sync.aligned.m8n8.x4.shared.b16 {%0,%1,%2,%3}, [%4];"
                 : "=r"(r[0]), "=r"(r[1]), "=r"(r[2]), "=r"(r[3]) : "r"(addr));
}
__device__ __forceinline__ void mma16816(float* d, const uint32_t* a, uint32_t b0, uint32_t b1) {
    asm volatile("mma.sync.aligned.m16n8k16.row.col.f32.f16.f16.f32 "
                 "{%0,%1,%2,%3}, {%4,%5,%6,%7}, {%8,%9}, {%0,%1,%2,%3};"
                 : "+f"(d[0]), "+f"(d[1]), "+f"(d[2]), "+f"(d[3])
                 : "r"(a[0]), "r"(a[1]), "r"(a[2]), "r"(a[3]), "r"(b0), "r"(b1));
}
#define CP_ASYNC16(dst, src) \
    asm volatile("cp.async.cg.shared.global [%0], [%1], 16;" :: "r"(dst), "l"(src) : "memory")
#define CP_COMMIT() asm volatile("cp.async.commit_group;" ::: "memory")
template <int N>
__device__ __forceinline__ void cp_wait() {
    asm volatile("cp.async.wait_group %0;" :: "n"(N) : "memory");
}
__device__ __forceinline__ void split1h(float v, __half& h, __half& l) {
    h = __float2half_rn(v);
    l = __float2half_rn(v - __half2float(h));
}

// ---------------------------------------------------------------------------
// fp16 warp-MMA GEMM: C[M,N] = A[M,K] @ B^T[N,K] + bias, then * outScale
//   NTERMS=1: A single, B single.      ah*bh
//   NTERMS=2: A split (Ah+Al), B single. ah*bh + al*bh
//   NTERMS=3: A split, B split.          + ah*bl
// Block tile 128x256, BK=64 fp16, 8 warps (2m x 4n), warp tile 64x64.
// cp.async stages: NT1=4, NT2=3, NT3=2 (all 216 KB smem). 144B padded rows.
// OUTM: 0 = fp32 C, 1 = split half Ch/Cl, 2 = single half Ch.
// ---------------------------------------------------------------------------
#define BM 128
#define BN 256
#define BK 64
#define ROWB 144
#define AMATB (128 * ROWB)          // 18432
#define BMATB (256 * ROWB)          // 36864
#define GSMEM 221184

template <int NTERMS>
__device__ __forceinline__ void produce_tile(
    uint32_t stb, const __half* pAh, const __half* pAl,
    const __half* pBh, const __half* pBl, long long K, int tid)
{
    constexpr int ACP = (NTERMS == 1) ? 1 : 2;
    const int pr = tid >> 3;          // 0..31
    const int pc = tid & 7;           // 0..7 (16B chunks across 128B row)
    const uint32_t dbase = (uint32_t)(pr * ROWB + pc * 16);
    const long long sbase = (long long)pr * K + pc * 8;
    #pragma unroll
    for (int i = 0; i < 4; i++) {     // A rows pr+32i
        uint32_t d = dbase + (uint32_t)(32 * i * ROWB);
        long long s = sbase + (long long)(32 * i) * K;
        CP_ASYNC16(stb + d, pAh + s);
        if (ACP == 2) CP_ASYNC16(stb + AMATB + d, pAl + s);
    }
    #pragma unroll
    for (int i = 0; i < 8; i++) {     // B rows pr+32i
        uint32_t d = dbase + (uint32_t)(32 * i * ROWB);
        long long s = sbase + (long long)(32 * i) * K;
        CP_ASYNC16(stb + ACP * AMATB + d, pBh + s);
        if (NTERMS == 3)
            CP_ASYNC16(stb + ACP * AMATB + BMATB + d, pBl + s);
    }
}

template <int NTERMS, int OUTM>
__global__ void __launch_bounds__(256, 1)
gemm_mma(const __half* __restrict__ Ah, const __half* __restrict__ Al,
         const __half* __restrict__ Bh, const __half* __restrict__ Bl,
         const float* __restrict__ bias, float outScale,
         float* __restrict__ C, __half* __restrict__ Ch, __half* __restrict__ Cl,
         int N, int K, long long sA, long long sB, long long sC)
{
    constexpr int ACP = (NTERMS == 1) ? 1 : 2;
    constexpr int BCP = (NTERMS == 3) ? 2 : 1;
    constexpr int STG = ACP * AMATB + BCP * BMATB;
    constexpr int NST = (NTERMS == 3) ? 2 : ((NTERMS == 2) ? 3 : 4);
    constexpr uint32_t OFF_ALO = AMATB;
    constexpr uint32_t OFF_B   = ACP * AMATB;
    constexpr uint32_t OFF_BLO = OFF_B + BMATB;

    extern __shared__ char sm[];
    const uint32_t sb = smem_u32(sm);
    const int tid = threadIdx.x;
    const int wid = tid >> 5;
    const int lane = tid & 31;
    const int wm = wid >> 2;          // 0..1
    const int wn = wid & 3;           // 0..3
    const long long m0 = blockIdx.y * BM;
    const long long n0 = blockIdx.x * BN;

    const __half* pAh = Ah + (long long)blockIdx.z * sA + m0 * K;
    const __half* pAl = (NTERMS >= 2) ? (Al + (long long)blockIdx.z * sA + m0 * K) : nullptr;
    const __half* pBh = Bh + (long long)blockIdx.z * sB + n0 * K;
    const __half* pBl = (NTERMS == 3) ? (Bl + (long long)blockIdx.z * sB + n0 * K) : nullptr;
    const long long zC = (long long)blockIdx.z * sC;

    const uint32_t lmo = (uint32_t)((lane & 15) * ROWB + (lane >> 4) * 16);

    float acc[4][8][4];
    #pragma unroll
    for (int i = 0; i < 4; i++)
        #pragma unroll
        for (int j = 0; j < 8; j++)
            #pragma unroll
            for (int q = 0; q < 4; q++) acc[i][j][q] = 0.0f;

    const int KT = K / BK;

    // prologue: stages 0..NST-2
    #pragma unroll
    for (int s = 0; s < NST - 1; s++) {
        produce_tile<NTERMS>(sb + (uint32_t)s * STG,
                             pAh + s * BK, (NTERMS >= 2) ? pAl + s * BK : nullptr,
                             pBh + s * BK, (NTERMS == 3) ? pBl + s * BK : nullptr, K, tid);
        CP_COMMIT();
    }

    for (int kt = 0; kt < KT; kt++) {
        cp_wait<NST - 2>();
        __syncthreads();

        const int nx = kt + NST - 1;
        if (nx < KT) {
            produce_tile<NTERMS>(sb + (uint32_t)(nx % NST) * STG,
                                 pAh + nx * BK, (NTERMS >= 2) ? pAl + nx * BK : nullptr,
                                 pBh + nx * BK, (NTERMS == 3) ? pBl + nx * BK : nullptr, K, tid);
        }
        CP_COMMIT();

        const uint32_t stb = sb + (uint32_t)(kt % NST) * STG;
        #pragma unroll
        for (int ks = 0; ks < 4; ks++) {
            const uint32_t kb = (uint32_t)(ks * 32);     // 16 halves * 2B
            uint32_t ah[4][4], al[4][4];
            #pragma unroll
            for (int mt = 0; mt < 4; mt++) {
                uint32_t rowb = (uint32_t)((wm * 64 + mt * 16) * ROWB);
                ldmx4(stb + rowb + lmo + kb, ah[mt]);
                if (NTERMS >= 2) ldmx4(stb + OFF_ALO + rowb + lmo + kb, al[mt]);
            }
            #pragma unroll
            for (int g = 0; g < 4; g++) {                // 16-col groups of warp's 64
                uint32_t rowb = (uint32_t)((wn * 64 + g * 16) * ROWB);
                uint32_t bh[4];
                ldmx4(stb + OFF_B + rowb + lmo + kb, bh);
                uint32_t bl[4];
                if (NTERMS == 3)
                    ldmx4(stb + OFF_BLO + rowb + lmo + kb, bl);
                #pragma unroll
                for (int mt = 0; mt < 4; mt++) {
                    #pragma unroll
                    for (int h = 0; h < 2; h++) {
                        const int nt = g * 2 + h;
                        mma16816(acc[mt][nt], ah[mt], bh[h], bh[h + 2]);       // hi*hi
                        if (NTERMS >= 2)
                            mma16816(acc[mt][nt], al[mt], bh[h], bh[h + 2]);   // lo*hi
                        if (NTERMS == 3)
                            mma16816(acc[mt][nt], ah[mt], bl[h], bl[h + 2]);   // hi*lo
                    }
                }
            }
        }
    }

    // epilogue
    const long long rb = m0 + wm * 64 + (lane >> 2);
    const long long cb = n0 + wn * 64 + (lane & 3) * 2;
    #pragma unroll
    for (int nt = 0; nt < 8; nt++) {
        const long long c = cb + nt * 8;
        float b0 = 0.0f, b1 = 0.0f;
        if (bias) { b0 = bias[c]; b1 = bias[c + 1]; }
        #pragma unroll
        for (int mt = 0; mt < 4; mt++) {
            const long long r = rb + mt * 16;
            float v00 = (acc[mt][nt][0] + b0) * outScale, v01 = (acc[mt][nt][1] + b1) * outScale;
            float v10 = (acc[mt][nt][2] + b0) * outScale, v11 = (acc[mt][nt][3] + b1) * outScale;
            if (OUTM == 0) {
                *(float2*)&C[zC + r * N + c]       = make_float2(v00, v01);
                *(float2*)&C[zC + (r + 8) * N + c] = make_float2(v10, v11);
            } else if (OUTM == 1) {
                __half h0, l0, h1, l1;
                split1h(v00, h0, l0); split1h(v01, h1, l1);
                *(__half2*)&Ch[zC + r * N + c] = __halves2half2(h0, h1);
                *(__half2*)&Cl[zC + r * N + c] = __halves2half2(l0, l1);
                split1h(v10, h0, l0); split1h(v11, h1, l1);
                *(__half2*)&Ch[zC + (r + 8) * N + c] = __halves2half2(h0, h1);
                *(__half2*)&Cl[zC + (r + 8) * N + c] = __halves2half2(l0, l1);
            } else {
                *(__half2*)&Ch[zC + r * N + c] =
                    __halves2half2(__float2half_rn(v00), __float2half_rn(v01));
                *(__half2*)&Ch[zC + (r + 8) * N + c] =
                    __halves2half2(__float2half_rn(v10), __float2half_rn(v11));
            }
        }
    }
}

// ---------------------------------------------------------------------------
// fp32 -> half split / round elementwise
// ---------------------------------------------------------------------------
__global__ void __launch_bounds__(256)
split_kernel(const float* __restrict__ src, __half* __restrict__ hi,
             __half* __restrict__ lo, long long n)
{
    long long i = ((long long)blockIdx.x * 256 + threadIdx.x) * 4;
    if (i >= n) return;
    float4 v = *(const float4*)(src + i);
    __half h, l;
    __half2 hv0, hv1, lv0, lv1;
    split1h(v.x, h, l); hv0.x = h; lv0.x = l;
    split1h(v.y, h, l); hv0.y = h; lv0.y = l;
    split1h(v.z, h, l); hv1.x = h; lv1.x = l;
    split1h(v.w, h, l); hv1.y = h; lv1.y = l;
    *(__half2*)(hi + i) = hv0;     *(__half2*)(hi + i + 2) = hv1;
    *(__half2*)(lo + i) = lv0;     *(__half2*)(lo + i + 2) = lv1;
}

__global__ void __launch_bounds__(256)
round_kernel(const float* __restrict__ src, __half* __restrict__ dst, long long n)
{
    long long i = ((long long)blockIdx.x * 256 + threadIdx.x) * 4;
    if (i >= n) return;
    float4 v = *(const float4*)(src + i);
    *(__half2*)(dst + i)     = __halves2half2(__float2half_rn(v.x), __float2half_rn(v.y));
    *(__half2*)(dst + i + 2) = __halves2half2(__float2half_rn(v.z), __float2half_rn(v.w));
}

// ---------------------------------------------------------------------------
// Row softmax: fp16 scaled logits in, fp32 math, fp16 probabilities out.
// ---------------------------------------------------------------------------
__global__ void __launch_bounds__(256)
softmax_kernel(const __half* __restrict__ lg, __half* __restrict__ outP)
{
    __shared__ float buf[S_LEN];
    __shared__ float red[256];
    const long long row = blockIdx.x;
    const __half* p = lg + row * S_LEN;
    const int tid = threadIdx.x;

    float mx = -1e30f;
    for (int i = tid * 2; i < S_LEN; i += 512) {
        __half2 hv = *(const __half2*)(p + i);
        float v0 = __half2float(hv.x), v1 = __half2float(hv.y);
        buf[i] = v0; buf[i + 1] = v1;
        mx = fmaxf(mx, fmaxf(v0, v1));
    }
    red[tid] = mx;
    __syncthreads();
    for (int s = 128; s > 0; s >>= 1) {
        if (tid < s) red[tid] = fmaxf(red[tid], red[tid + s]);
        __syncthreads();
    }
    mx = red[0];
    __syncthreads();

    float sum = 0.0f;
    for (int i = tid; i < S_LEN; i += 256) {
        float e = __expf(buf[i] - mx);
        buf[i] = e;
        sum += e;
    }
    red[tid] = sum;
    __syncthreads();
    for (int s = 128; s > 0; s >>= 1) {
        if (tid < s) red[tid] += red[tid + s];
        __syncthreads();
    }
    float inv = 1.0f / red[0];

    __half* op = outP + row * S_LEN;
    for (int i = tid * 2; i < S_LEN; i += 512) {
        *(__half2*)(op + i) = __halves2half2(__float2half_rn(buf[i] * inv),
                                             __float2half_rn(buf[i + 1] * inv));
    }
}

// ---------------------------------------------------------------------------
// Per-batch tiled transpose fp32 [R,C] -> half [C,R]; single or split output.
// ---------------------------------------------------------------------------
__global__ void __launch_bounds__(256)
transpose_h_kernel(const float* __restrict__ src, __half* __restrict__ dst, int R, int C)
{
    __shared__ float t[32][33];
    const long long bofs = (long long)blockIdx.z * R * C;
    src += bofs; dst += bofs;
    int c0 = blockIdx.x * 32, r0 = blockIdx.y * 32;
    for (int i = threadIdx.y; i < 32; i += 8)
        t[i][threadIdx.x] = src[(long long)(r0 + i) * C + c0 + threadIdx.x];
    __syncthreads();
    for (int i = threadIdx.y; i < 32; i += 8)
        dst[(long long)(c0 + i) * R + r0 + threadIdx.x] = __float2half_rn(t[threadIdx.x][i]);
}

__global__ void __launch_bounds__(256)
transpose_split_kernel(const float* __restrict__ src, __half* __restrict__ dstH,
                       __half* __restrict__ dstL, int R, int C)
{
    __shared__ float t[32][33];
    const long long bofs = (long long)blockIdx.z * R * C;
    src += bofs; dstH += bofs; dstL += bofs;
    int c0 = blockIdx.x * 32, r0 = blockIdx.y * 32;
    for (int i = threadIdx.y; i < 32; i += 8)
        t[i][threadIdx.x] = src[(long long)(r0 + i) * C + c0 + threadIdx.x];
    __syncthreads();
    for (int i = threadIdx.y; i < 32; i += 8) {
        __half h, l;
        split1h(t[threadIdx.x][i], h, l);
        long long o = (long long)(c0 + i) * R + r0 + threadIdx.x;
        dstH[o] = h;
        dstL[o] = l;
    }
}

// ---------------------------------------------------------------------------
extern "C" void kernel_launch(void* const* d_in, const int* in_sizes, int n_in,
                              void* d_out, int out_size)
{
    const float* x  = (const float*)d_in[0];
    const float* Wq = (const float*)d_in[1];
    const float* bq = (const float*)d_in[2];
    const float* Wk = (const float*)d_in[3];
    const float* bk = (const float*)d_in[4];
    const float* Wv = (const float*)d_in[5];
    const float* bv = (const float*)d_in[6];
    const float* Wc = (const float*)d_in[7];
    const float* bc = (const float*)d_in[8];
    float* out = (float*)d_out;

    float *V, *Y;
    __half *attLg, *attP, *xH, *xL, *QH, *QL, *KH, *VtH, *YpH, *YpL;
    __half *WqH, *WkH, *WvH, *WvL, *WcH, *WcL;
    cudaGetSymbolAddress((void**)&attLg, g_attLg);
    cudaGetSymbolAddress((void**)&attP,  g_attP);
    cudaGetSymbolAddress((void**)&xH,    g_xH);
    cudaGetSymbolAddress((void**)&xL,    g_xL);
    cudaGetSymbolAddress((void**)&QH,    g_QH);
    cudaGetSymbolAddress((void**)&QL,    g_QL);
    cudaGetSymbolAddress((void**)&KH,    g_KH);
    cudaGetSymbolAddress((void**)&V,     g_V);
    cudaGetSymbolAddress((void**)&Y,     g_Y);
    cudaGetSymbolAddress((void**)&VtH,   g_VtH);
    cudaGetSymbolAddress((void**)&YpH,   g_YpH);
    cudaGetSymbolAddress((void**)&YpL,   g_YpL);
    cudaGetSymbolAddress((void**)&WqH,   g_WqH);
    cudaGetSymbolAddress((void**)&WkH,   g_WkH);
    cudaGetSymbolAddress((void**)&WvH,   g_WvH);
    cudaGetSymbolAddress((void**)&WvL,   g_WvL);
    cudaGetSymbolAddress((void**)&WcH,   g_WcH);
    cudaGetSymbolAddress((void**)&WcL,   g_WcL);

    cudaFuncSetAttribute(gemm_mma<1,0>, cudaFuncAttributeMaxDynamicSharedMemorySize, GSMEM);
    cudaFuncSetAttribute(gemm_mma<2,1>, cudaFuncAttributeMaxDynamicSharedMemorySize, GSMEM);
    cudaFuncSetAttribute(gemm_mma<2,2>, cudaFuncAttributeMaxDynamicSharedMemorySize, GSMEM);
    cudaFuncSetAttribute(gemm_mma<3,0>, cudaFuncAttributeMaxDynamicSharedMemorySize, GSMEM);

    const float scale = 0.03608439182435161f;   // 768^-0.5
    const long long sd = (long long)S_LEN * D_DIM;
    dim3 blk(256);
    dim3 tblk(32, 8);

    // ---- operand prep ----
    split_kernel<<<(BSD / 4 + 255) / 256, blk>>>(x, xH, xL, BSD);
    round_kernel<<<(DD / 4 + 255) / 256, blk>>>(Wq, WqH, DD);
    round_kernel<<<(DD / 4 + 255) / 256, blk>>>(Wk, WkH, DD);
    split_kernel<<<(DD / 4 + 255) / 256, blk>>>(Wv, WvH, WvL, DD);
    split_kernel<<<(DD / 4 + 255) / 256, blk>>>(Wc, WcH, WcL, DD);

    // ---- projections ----  (Q carries the softmax scale)
    dim3 gp(D_DIM / BN, M_TOT / BM, 1);                  // (3,128,1)
    gemm_mma<2,1><<<gp, blk, GSMEM>>>(xH, xL, WqH, nullptr, bq, scale, nullptr, QH, QL,
                                      D_DIM, D_DIM, 0, 0, 0);
    gemm_mma<2,2><<<gp, blk, GSMEM>>>(xH, xL, WkH, nullptr, bk, 1.0f, nullptr, KH, nullptr,
                                      D_DIM, D_DIM, 0, 0, 0);
    gemm_mma<3,0><<<gp, blk, GSMEM>>>(xH, xL, WvH, WvL, bv, 1.0f, V, nullptr, nullptr,
                                      D_DIM, D_DIM, 0, 0, 0);

    // ---- scaled logits[b] = (scale*Q[b]) @ K[b]^T, written as fp16 ----
    dim3 ga(S_LEN / BN, S_LEN / BM, B_BATCH);            // (16,32,4)
    gemm_mma<2,2><<<ga, blk, GSMEM>>>(QH, QL, KH, nullptr, nullptr, 1.0f,
                                      nullptr, attLg, nullptr,
                                      S_LEN, D_DIM, sd, sd, SSLL);

    // ---- softmax: fp16 logits -> fp16 probabilities ----
    softmax_kernel<<<M_TOT, blk>>>(attLg, attP);

    // ---- V^T per batch (single half) ----
    dim3 gt(D_DIM / 32, S_LEN / 32, B_BATCH);            // (24,128,4)
    transpose_h_kernel<<<gt, tblk>>>(V, VtH, S_LEN, D_DIM);

    // ---- Y[b] = att[b] @ Vt[b]^T  (1-term fp16) ----
    dim3 gy(D_DIM / BN, S_LEN / BM, B_BATCH);            // (3,32,4)
    gemm_mma<1,0><<<gy, blk, GSMEM>>>(attP, nullptr, VtH, nullptr, nullptr, 1.0f,
                                      Y, nullptr, nullptr,
                                      D_DIM, S_LEN, SSLL, sd, sd);

    // ---- permutation (per-batch transpose) + split ----
    transpose_split_kernel<<<gt, tblk>>>(Y, YpH, YpL, S_LEN, D_DIM);

    // ---- output projection -> d_out (3-term, accurate) ----
    gemm_mma<3,0><<<gp, blk, GSMEM>>>(YpH, YpL, WcH, WcL, bc, 1.0f, out, nullptr, nullptr,
                                      D_DIM, D_DIM, 0, 0, 0);
}

// round 11
// speedup vs baseline: 2.2191x; 1.2795x over previous
#include <cuda_runtime.h>
#include <cuda_fp16.h>
#include <stdint.h>

// ---------------------------------------------------------------------------
// Problem constants
// ---------------------------------------------------------------------------
#define D_DIM 768
#define S_LEN 4096
#define B_BATCH 4
#define M_TOT (B_BATCH * S_LEN)            // 16384
#define BSD (B_BATCH * S_LEN * D_DIM)
#define SSLL ((long long)S_LEN * S_LEN)
#define ATT_N ((size_t)B_BATCH * S_LEN * S_LEN)
#define DD (D_DIM * D_DIM)

// ---------------------------------------------------------------------------
// Static device scratch
// ---------------------------------------------------------------------------
__device__ __align__(256) __half g_attLg[ATT_N];              // scaled fp16 logits
__device__ __align__(256) __half g_attP[ATT_N];               // fp16 probabilities
__device__ __align__(256) __half g_xH[BSD], g_xL[BSD];
__device__ __align__(256) __half g_QH[BSD];                   // Q pre-scaled by 768^-0.5
__device__ __align__(256) __half g_KH[BSD];
__device__ __align__(256) __half g_VH[BSD];
__device__ __align__(256) __half g_VtH[BSD];
__device__ __align__(256) float  g_Y[BSD];
__device__ __align__(256) __half g_YpH[BSD], g_YpL[BSD];
__device__ __align__(256) __half g_WqH[DD], g_WkH[DD], g_WvH[DD], g_WcH[DD];

// ---------------------------------------------------------------------------
// helpers
// ---------------------------------------------------------------------------
__device__ __forceinline__ uint32_t smem_u32(const void* p) {
    uint32_t a;
    asm("{ .reg .u64 t; cvta.to.shared.u64 t, %1; cvt.u32.u64 %0, t; }" : "=r"(a) : "l"(p));
    return a;
}
__device__ __forceinline__ void ldmx4(uint32_t addr, uint32_t* r) {
    asm volatile("ldmatrix.sync.aligned.m8n8.x4.shared.b16 {%0,%1,%2,%3}, [%4];"
                 : "=r"(r[0]), "=r"(r[1]), "=r"(r[2]), "=r"(r[3]) : "r"(addr));
}
__device__ __forceinline__ void mma16816(float* d, const uint32_t* a, uint32_t b0, uint32_t b1) {
    asm volatile("mma.sync.aligned.m16n8k16.row.col.f32.f16.f16.f32 "
                 "{%0,%1,%2,%3}, {%4,%5,%6,%7}, {%8,%9}, {%0,%1,%2,%3};"
                 : "+f"(d[0]), "+f"(d[1]), "+f"(d[2]), "+f"(d[3])
                 : "r"(a[0]), "r"(a[1]), "r"(a[2]), "r"(a[3]), "r"(b0), "r"(b1));
}
#define CP_ASYNC16(dst, src) \
    asm volatile("cp.async.cg.shared.global [%0], [%1], 16;" :: "r"(dst), "l"(src) : "memory")
#define CP_COMMIT() asm volatile("cp.async.commit_group;" ::: "memory")
template <int N>
__device__ __forceinline__ void cp_wait() {
    asm volatile("cp.async.wait_group %0;" :: "n"(N) : "memory");
}
__device__ __forceinline__ void split1h(float v, __half& h, __half& l) {
    h = __float2half_rn(v);
    l = __float2half_rn(v - __half2float(h));
}

// ---------------------------------------------------------------------------
// fp16 warp-MMA GEMM: C[M,N] = A[M,K] @ B^T[N,K] + bias, then * outScale
//   NTERMS=1: A single, B single.        ah*bh
//   NTERMS=2: A split (Ah+Al), B single. ah*bh + al*bh
//   NTERMS=3: A split, B split.          + ah*bl
// Block tile 128x256, BK=64 fp16, 8 warps (2m x 4n), warp tile 64x64.
// cp.async stages: NT1=4, NT2=3, NT3=2 (all 216 KB smem). 144B padded rows.
// OUTM: 0 = fp32 C, 1 = split half Ch/Cl, 2 = single half Ch.
// ---------------------------------------------------------------------------
#define BM 128
#define BN 256
#define BK 64
#define ROWB 144
#define AMATB (128 * ROWB)          // 18432
#define BMATB (256 * ROWB)          // 36864
#define GSMEM 221184

template <int NTERMS>
__device__ __forceinline__ void produce_tile(
    uint32_t stb, const __half* pAh, const __half* pAl,
    const __half* pBh, const __half* pBl, long long K, int tid)
{
    constexpr int ACP = (NTERMS == 1) ? 1 : 2;
    const int pr = tid >> 3;          // 0..31
    const int pc = tid & 7;           // 0..7 (16B chunks across 128B row)
    const uint32_t dbase = (uint32_t)(pr * ROWB + pc * 16);
    const long long sbase = (long long)pr * K + pc * 8;
    #pragma unroll
    for (int i = 0; i < 4; i++) {     // A rows pr+32i
        uint32_t d = dbase + (uint32_t)(32 * i * ROWB);
        long long s = sbase + (long long)(32 * i) * K;
        CP_ASYNC16(stb + d, pAh + s);
        if (ACP == 2) CP_ASYNC16(stb + AMATB + d, pAl + s);
    }
    #pragma unroll
    for (int i = 0; i < 8; i++) {     // B rows pr+32i
        uint32_t d = dbase + (uint32_t)(32 * i * ROWB);
        long long s = sbase + (long long)(32 * i) * K;
        CP_ASYNC16(stb + ACP * AMATB + d, pBh + s);
        if (NTERMS == 3)
            CP_ASYNC16(stb + ACP * AMATB + BMATB + d, pBl + s);
    }
}

template <int NTERMS, int OUTM>
__global__ void __launch_bounds__(256, 1)
gemm_mma(const __half* __restrict__ Ah, const __half* __restrict__ Al,
         const __half* __restrict__ Bh, const __half* __restrict__ Bl,
         const float* __restrict__ bias, float outScale,
         float* __restrict__ C, __half* __restrict__ Ch, __half* __restrict__ Cl,
         int N, int K, long long sA, long long sB, long long sC)
{
    constexpr int ACP = (NTERMS == 1) ? 1 : 2;
    constexpr int BCP = (NTERMS == 3) ? 2 : 1;
    constexpr int STG = ACP * AMATB + BCP * BMATB;
    constexpr int NST = (NTERMS == 3) ? 2 : ((NTERMS == 2) ? 3 : 4);
    constexpr uint32_t OFF_ALO = AMATB;
    constexpr uint32_t OFF_B   = ACP * AMATB;
    constexpr uint32_t OFF_BLO = OFF_B + BMATB;

    extern __shared__ char sm[];
    const uint32_t sb = smem_u32(sm);
    const int tid = threadIdx.x;
    const int wid = tid >> 5;
    const int lane = tid & 31;
    const int wm = wid >> 2;          // 0..1
    const int wn = wid & 3;           // 0..3
    const long long m0 = blockIdx.y * BM;
    const long long n0 = blockIdx.x * BN;

    const __half* pAh = Ah + (long long)blockIdx.z * sA + m0 * K;
    const __half* pAl = (NTERMS >= 2) ? (Al + (long long)blockIdx.z * sA + m0 * K) : nullptr;
    const __half* pBh = Bh + (long long)blockIdx.z * sB + n0 * K;
    const __half* pBl = (NTERMS == 3) ? (Bl + (long long)blockIdx.z * sB + n0 * K) : nullptr;
    const long long zC = (long long)blockIdx.z * sC;

    const uint32_t lmo = (uint32_t)((lane & 15) * ROWB + (lane >> 4) * 16);

    float acc[4][8][4];
    #pragma unroll
    for (int i = 0; i < 4; i++)
        #pragma unroll
        for (int j = 0; j < 8; j++)
            #pragma unroll
            for (int q = 0; q < 4; q++) acc[i][j][q] = 0.0f;

    const int KT = K / BK;

    // prologue: stages 0..NST-2
    #pragma unroll
    for (int s = 0; s < NST - 1; s++) {
        produce_tile<NTERMS>(sb + (uint32_t)s * STG,
                             pAh + s * BK, (NTERMS >= 2) ? pAl + s * BK : nullptr,
                             pBh + s * BK, (NTERMS == 3) ? pBl + s * BK : nullptr, K, tid);
        CP_COMMIT();
    }

    for (int kt = 0; kt < KT; kt++) {
        cp_wait<NST - 2>();
        __syncthreads();

        const int nx = kt + NST - 1;
        if (nx < KT) {
            produce_tile<NTERMS>(sb + (uint32_t)(nx % NST) * STG,
                                 pAh + nx * BK, (NTERMS >= 2) ? pAl + nx * BK : nullptr,
                                 pBh + nx * BK, (NTERMS == 3) ? pBl + nx * BK : nullptr, K, tid);
        }
        CP_COMMIT();

        const uint32_t stb = sb + (uint32_t)(kt % NST) * STG;
        #pragma unroll
        for (int ks = 0; ks < 4; ks++) {
            const uint32_t kb = (uint32_t)(ks * 32);     // 16 halves * 2B
            uint32_t ah[4][4], al[4][4];
            #pragma unroll
            for (int mt = 0; mt < 4; mt++) {
                uint32_t rowb = (uint32_t)((wm * 64 + mt * 16) * ROWB);
                ldmx4(stb + rowb + lmo + kb, ah[mt]);
                if (NTERMS >= 2) ldmx4(stb + OFF_ALO + rowb + lmo + kb, al[mt]);
            }
            #pragma unroll
            for (int g = 0; g < 4; g++) {                // 16-col groups of warp's 64
                uint32_t rowb = (uint32_t)((wn * 64 + g * 16) * ROWB);
                uint32_t bh[4];
                ldmx4(stb + OFF_B + rowb + lmo + kb, bh);
                uint32_t bl[4];
                if (NTERMS == 3)
                    ldmx4(stb + OFF_BLO + rowb + lmo + kb, bl);
                #pragma unroll
                for (int mt = 0; mt < 4; mt++) {
                    #pragma unroll
                    for (int h = 0; h < 2; h++) {
                        const int nt = g * 2 + h;
                        mma16816(acc[mt][nt], ah[mt], bh[h], bh[h + 2]);       // hi*hi
                        if (NTERMS >= 2)
                            mma16816(acc[mt][nt], al[mt], bh[h], bh[h + 2]);   // lo*hi
                        if (NTERMS == 3)
                            mma16816(acc[mt][nt], ah[mt], bl[h], bl[h + 2]);   // hi*lo
                    }
                }
            }
        }
    }

    // epilogue
    const long long rb = m0 + wm * 64 + (lane >> 2);
    const long long cb = n0 + wn * 64 + (lane & 3) * 2;
    #pragma unroll
    for (int nt = 0; nt < 8; nt++) {
        const long long c = cb + nt * 8;
        float b0 = 0.0f, b1 = 0.0f;
        if (bias) { b0 = bias[c]; b1 = bias[c + 1]; }
        #pragma unroll
        for (int mt = 0; mt < 4; mt++) {
            const long long r = rb + mt * 16;
            float v00 = (acc[mt][nt][0] + b0) * outScale, v01 = (acc[mt][nt][1] + b1) * outScale;
            float v10 = (acc[mt][nt][2] + b0) * outScale, v11 = (acc[mt][nt][3] + b1) * outScale;
            if (OUTM == 0) {
                *(float2*)&C[zC + r * N + c]       = make_float2(v00, v01);
                *(float2*)&C[zC + (r + 8) * N + c] = make_float2(v10, v11);
            } else if (OUTM == 1) {
                __half h0, l0, h1, l1;
                split1h(v00, h0, l0); split1h(v01, h1, l1);
                *(__half2*)&Ch[zC + r * N + c] = __halves2half2(h0, h1);
                *(__half2*)&Cl[zC + r * N + c] = __halves2half2(l0, l1);
                split1h(v10, h0, l0); split1h(v11, h1, l1);
                *(__half2*)&Ch[zC + (r + 8) * N + c] = __halves2half2(h0, h1);
                *(__half2*)&Cl[zC + (r + 8) * N + c] = __halves2half2(l0, l1);
            } else {
                *(__half2*)&Ch[zC + r * N + c] =
                    __halves2half2(__float2half_rn(v00), __float2half_rn(v01));
                *(__half2*)&Ch[zC + (r + 8) * N + c] =
                    __halves2half2(__float2half_rn(v10), __float2half_rn(v11));
            }
        }
    }
}

// ---------------------------------------------------------------------------
// fp32 -> half split / round elementwise
// ---------------------------------------------------------------------------
__global__ void __launch_bounds__(256)
split_kernel(const float* __restrict__ src, __half* __restrict__ hi,
             __half* __restrict__ lo, long long n)
{
    long long i = ((long long)blockIdx.x * 256 + threadIdx.x) * 4;
    if (i >= n) return;
    float4 v = *(const float4*)(src + i);
    __half h, l;
    __half2 hv0, hv1, lv0, lv1;
    split1h(v.x, h, l); hv0.x = h; lv0.x = l;
    split1h(v.y, h, l); hv0.y = h; lv0.y = l;
    split1h(v.z, h, l); hv1.x = h; lv1.x = l;
    split1h(v.w, h, l); hv1.y = h; lv1.y = l;
    *(__half2*)(hi + i) = hv0;     *(__half2*)(hi + i + 2) = hv1;
    *(__half2*)(lo + i) = lv0;     *(__half2*)(lo + i + 2) = lv1;
}

__global__ void __launch_bounds__(256)
round_kernel(const float* __restrict__ src, __half* __restrict__ dst, long long n)
{
    long long i = ((long long)blockIdx.x * 256 + threadIdx.x) * 4;
    if (i >= n) return;
    float4 v = *(const float4*)(src + i);
    *(__half2*)(dst + i)     = __halves2half2(__float2half_rn(v.x), __float2half_rn(v.y));
    *(__half2*)(dst + i + 2) = __halves2half2(__float2half_rn(v.z), __float2half_rn(v.w));
}

// ---------------------------------------------------------------------------
// Row softmax: fp16 scaled logits in, fp32 math, fp16 probabilities out.
// ---------------------------------------------------------------------------
__global__ void __launch_bounds__(256)
softmax_kernel(const __half* __restrict__ lg, __half* __restrict__ outP)
{
    __shared__ float buf[S_LEN];
    __shared__ float red[256];
    const long long row = blockIdx.x;
    const __half* p = lg + row * S_LEN;
    const int tid = threadIdx.x;

    float mx = -1e30f;
    for (int i = tid * 2; i < S_LEN; i += 512) {
        __half2 hv = *(const __half2*)(p + i);
        float v0 = __half2float(hv.x), v1 = __half2float(hv.y);
        buf[i] = v0; buf[i + 1] = v1;
        mx = fmaxf(mx, fmaxf(v0, v1));
    }
    red[tid] = mx;
    __syncthreads();
    for (int s = 128; s > 0; s >>= 1) {
        if (tid < s) red[tid] = fmaxf(red[tid], red[tid + s]);
        __syncthreads();
    }
    mx = red[0];
    __syncthreads();

    float sum = 0.0f;
    for (int i = tid; i < S_LEN; i += 256) {
        float e = __expf(buf[i] - mx);
        buf[i] = e;
        sum += e;
    }
    red[tid] = sum;
    __syncthreads();
    for (int s = 128; s > 0; s >>= 1) {
        if (tid < s) red[tid] += red[tid + s];
        __syncthreads();
    }
    float inv = 1.0f / red[0];

    __half* op = outP + row * S_LEN;
    for (int i = tid * 2; i < S_LEN; i += 512) {
        *(__half2*)(op + i) = __halves2half2(__float2half_rn(buf[i] * inv),
                                             __float2half_rn(buf[i + 1] * inv));
    }
}

// ---------------------------------------------------------------------------
// Per-batch tiled transposes.
// ---------------------------------------------------------------------------
__global__ void __launch_bounds__(256)
transpose_hh_kernel(const __half* __restrict__ src, __half* __restrict__ dst, int R, int C)
{
    __shared__ __half t[32][34];
    const long long bofs = (long long)blockIdx.z * R * C;
    src += bofs; dst += bofs;
    int c0 = blockIdx.x * 32, r0 = blockIdx.y * 32;
    for (int i = threadIdx.y; i < 32; i += 8)
        t[i][threadIdx.x] = src[(long long)(r0 + i) * C + c0 + threadIdx.x];
    __syncthreads();
    for (int i = threadIdx.y; i < 32; i += 8)
        dst[(long long)(c0 + i) * R + r0 + threadIdx.x] = t[threadIdx.x][i];
}

__global__ void __launch_bounds__(256)
transpose_split_kernel(const float* __restrict__ src, __half* __restrict__ dstH,
                       __half* __restrict__ dstL, int R, int C)
{
    __shared__ float t[32][33];
    const long long bofs = (long long)blockIdx.z * R * C;
    src += bofs; dstH += bofs; dstL += bofs;
    int c0 = blockIdx.x * 32, r0 = blockIdx.y * 32;
    for (int i = threadIdx.y; i < 32; i += 8)
        t[i][threadIdx.x] = src[(long long)(r0 + i) * C + c0 + threadIdx.x];
    __syncthreads();
    for (int i = threadIdx.y; i < 32; i += 8) {
        __half h, l;
        split1h(t[threadIdx.x][i], h, l);
        long long o = (long long)(c0 + i) * R + r0 + threadIdx.x;
        dstH[o] = h;
        dstL[o] = l;
    }
}

// ---------------------------------------------------------------------------
extern "C" void kernel_launch(void* const* d_in, const int* in_sizes, int n_in,
                              void* d_out, int out_size)
{
    const float* x  = (const float*)d_in[0];
    const float* Wq = (const float*)d_in[1];
    const float* bq = (const float*)d_in[2];
    const float* Wk = (const float*)d_in[3];
    const float* bk = (const float*)d_in[4];
    const float* Wv = (const float*)d_in[5];
    const float* bv = (const float*)d_in[6];
    const float* Wc = (const float*)d_in[7];
    const float* bc = (const float*)d_in[8];
    float* out = (float*)d_out;

    float *Y;
    __half *attLg, *attP, *xH, *xL, *QH, *KH, *VH, *VtH, *YpH, *YpL;
    __half *WqH, *WkH, *WvH, *WcH;
    cudaGetSymbolAddress((void**)&attLg, g_attLg);
    cudaGetSymbolAddress((void**)&attP,  g_attP);
    cudaGetSymbolAddress((void**)&xH,    g_xH);
    cudaGetSymbolAddress((void**)&xL,    g_xL);
    cudaGetSymbolAddress((void**)&QH,    g_QH);
    cudaGetSymbolAddress((void**)&KH,    g_KH);
    cudaGetSymbolAddress((void**)&VH,    g_VH);
    cudaGetSymbolAddress((void**)&VtH,   g_VtH);
    cudaGetSymbolAddress((void**)&Y,     g_Y);
    cudaGetSymbolAddress((void**)&YpH,   g_YpH);
    cudaGetSymbolAddress((void**)&YpL,   g_YpL);
    cudaGetSymbolAddress((void**)&WqH,   g_WqH);
    cudaGetSymbolAddress((void**)&WkH,   g_WkH);
    cudaGetSymbolAddress((void**)&WvH,   g_WvH);
    cudaGetSymbolAddress((void**)&WcH,   g_WcH);

    cudaFuncSetAttribute(gemm_mma<1,0>, cudaFuncAttributeMaxDynamicSharedMemorySize, GSMEM);
    cudaFuncSetAttribute(gemm_mma<1,2>, cudaFuncAttributeMaxDynamicSharedMemorySize, GSMEM);
    cudaFuncSetAttribute(gemm_mma<2,0>, cudaFuncAttributeMaxDynamicSharedMemorySize, GSMEM);
    cudaFuncSetAttribute(gemm_mma<2,2>, cudaFuncAttributeMaxDynamicSharedMemorySize, GSMEM);

    const float scale = 0.03608439182435161f;   // 768^-0.5
    const long long sd = (long long)S_LEN * D_DIM;
    dim3 blk(256);
    dim3 tblk(32, 8);

    // ---- operand prep ----
    split_kernel<<<(BSD / 4 + 255) / 256, blk>>>(x, xH, xL, BSD);
    round_kernel<<<(DD / 4 + 255) / 256, blk>>>(Wq, WqH, DD);
    round_kernel<<<(DD / 4 + 255) / 256, blk>>>(Wk, WkH, DD);
    round_kernel<<<(DD / 4 + 255) / 256, blk>>>(Wv, WvH, DD);
    round_kernel<<<(DD / 4 + 255) / 256, blk>>>(Wc, WcH, DD);

    // ---- projections (all 2-term, single-half outputs; Q carries the scale) ----
    dim3 gp(D_DIM / BN, M_TOT / BM, 1);                  // (3,128,1)
    gemm_mma<2,2><<<gp, blk, GSMEM>>>(xH, xL, WqH, nullptr, bq, scale, nullptr, QH, nullptr,
                                      D_DIM, D_DIM, 0, 0, 0);
    gemm_mma<2,2><<<gp, blk, GSMEM>>>(xH, xL, WkH, nullptr, bk, 1.0f, nullptr, KH, nullptr,
                                      D_DIM, D_DIM, 0, 0, 0);
    gemm_mma<2,2><<<gp, blk, GSMEM>>>(xH, xL, WvH, nullptr, bv, 1.0f, nullptr, VH, nullptr,
                                      D_DIM, D_DIM, 0, 0, 0);

    // ---- scaled logits[b] = (scale*Q[b]) @ K[b]^T  (1-term, fp16 out) ----
    dim3 ga(S_LEN / BN, S_LEN / BM, B_BATCH);            // (16,32,4)
    gemm_mma<1,2><<<ga, blk, GSMEM>>>(QH, nullptr, KH, nullptr, nullptr, 1.0f,
                                      nullptr, attLg, nullptr,
                                      S_LEN, D_DIM, sd, sd, SSLL);

    // ---- softmax: fp16 logits -> fp16 probabilities ----
    softmax_kernel<<<M_TOT, blk>>>(attLg, attP);

    // ---- V^T per batch (half -> half) ----
    dim3 gt(D_DIM / 32, S_LEN / 32, B_BATCH);            // (24,128,4)
    transpose_hh_kernel<<<gt, tblk>>>(VH, VtH, S_LEN, D_DIM);

    // ---- Y[b] = att[b] @ Vt[b]^T  (1-term fp16) ----
    dim3 gy(D_DIM / BN, S_LEN / BM, B_BATCH);            // (3,32,4)
    gemm_mma<1,0><<<gy, blk, GSMEM>>>(attP, nullptr, VtH, nullptr, nullptr, 1.0f,
                                      Y, nullptr, nullptr,
                                      D_DIM, S_LEN, SSLL, sd, sd);

    // ---- permutation (per-batch transpose) + split ----
    transpose_split_kernel<<<gt, tblk>>>(Y, YpH, YpL, S_LEN, D_DIM);

    // ---- output projection -> d_out (2-term: Yp split x Wc single) ----
    gemm_mma<2,0><<<gp, blk, GSMEM>>>(YpH, YpL, WcH, nullptr, bc, 1.0f, out, nullptr, nullptr,
                                      D_DIM, D_DIM, 0, 0, 0);
}

// round 12
// speedup vs baseline: 2.7149x; 1.2234x over previous
#include <cuda_runtime.h>
#include <cuda_fp16.h>
#include <stdint.h>

// ---------------------------------------------------------------------------
// Problem constants
// ---------------------------------------------------------------------------
#define D_DIM 768
#define S_LEN 4096
#define B_BATCH 4
#define M_TOT (B_BATCH * S_LEN)            // 16384
#define BSD (B_BATCH * S_LEN * D_DIM)
#define SSLL ((long long)S_LEN * S_LEN)
#define ATT_N ((size_t)B_BATCH * S_LEN * S_LEN)
#define DD (D_DIM * D_DIM)

// ---------------------------------------------------------------------------
// Static device scratch (all fp16)
// ---------------------------------------------------------------------------
__device__ __align__(256) __half g_attLg[ATT_N];              // scaled fp16 logits
__device__ __align__(256) __half g_attP[ATT_N];               // fp16 probabilities
__device__ __align__(256) __half g_xH[BSD];
__device__ __align__(256) __half g_QH[BSD];                   // pre-scaled by 768^-0.5
__device__ __align__(256) __half g_KH[BSD];
__device__ __align__(256) __half g_VH[BSD];
__device__ __align__(256) __half g_VtH[BSD];
__device__ __align__(256) __half g_YH[BSD];
__device__ __align__(256) __half g_YpH[BSD];
__device__ __align__(256) __half g_WqH[DD], g_WkH[DD], g_WvH[DD], g_WcH[DD];

// ---------------------------------------------------------------------------
// helpers
// ---------------------------------------------------------------------------
__device__ __forceinline__ uint32_t smem_u32(const void* p) {
    uint32_t a;
    asm("{ .reg .u64 t; cvta.to.shared.u64 t, %1; cvt.u32.u64 %0, t; }" : "=r"(a) : "l"(p));
    return a;
}
__device__ __forceinline__ void ldmx4(uint32_t addr, uint32_t* r) {
    asm volatile("ldmatrix.sync.aligned.m8n8.x4.shared.b16 {%0,%1,%2,%3}, [%4];"
                 : "=r"(r[0]), "=r"(r[1]), "=r"(r[2]), "=r"(r[3]) : "r"(addr));
}
__device__ __forceinline__ void mma16816(float* d, const uint32_t* a, uint32_t b0, uint32_t b1) {
    asm volatile("mma.sync.aligned.m16n8k16.row.col.f32.f16.f16.f32 "
                 "{%0,%1,%2,%3}, {%4,%5,%6,%7}, {%8,%9}, {%0,%1,%2,%3};"
                 : "+f"(d[0]), "+f"(d[1]), "+f"(d[2]), "+f"(d[3])
                 : "r"(a[0]), "r"(a[1]), "r"(a[2]), "r"(a[3]), "r"(b0), "r"(b1));
}
#define CP_ASYNC16(dst, src) \
    asm volatile("cp.async.cg.shared.global [%0], [%1], 16;" :: "r"(dst), "l"(src) : "memory")
#define CP_COMMIT() asm volatile("cp.async.commit_group;" ::: "memory")
template <int N>
__device__ __forceinline__ void cp_wait() {
    asm volatile("cp.async.wait_group %0;" :: "n"(N) : "memory");
}

// ---------------------------------------------------------------------------
// fp16 1-term warp-MMA GEMM: C[M,N] = A[M,K] @ B^T[N,K] + bias, then * outScale
// Block tile 128x256, BK=64 fp16, 8 warps (2m x 4n), warp tile 64x64.
// 4-stage cp.async pipeline (216 KB smem). 144B padded rows.
// OUTM: 0 = fp32 C, 2 = single half Ch.
// ---------------------------------------------------------------------------
#define BM 128
#define BN 256
#define BK 64
#define ROWB 144
#define AMATB (128 * ROWB)          // 18432
#define BMATB (256 * ROWB)          // 36864
#define STG (AMATB + BMATB)         // 55296
#define NST 4
#define GSMEM (NST * STG)           // 221184

__device__ __forceinline__ void produce_tile(
    uint32_t stb, const __half* pAh, const __half* pBh, long long K, int tid)
{
    const int pr = tid >> 3;          // 0..31
    const int pc = tid & 7;           // 0..7 (16B chunks across 128B row)
    const uint32_t dbase = (uint32_t)(pr * ROWB + pc * 16);
    const long long sbase = (long long)pr * K + pc * 8;
    #pragma unroll
    for (int i = 0; i < 4; i++) {     // A rows pr+32i
        uint32_t d = dbase + (uint32_t)(32 * i * ROWB);
        long long s = sbase + (long long)(32 * i) * K;
        CP_ASYNC16(stb + d, pAh + s);
    }
    #pragma unroll
    for (int i = 0; i < 8; i++) {     // B rows pr+32i
        uint32_t d = dbase + (uint32_t)(32 * i * ROWB);
        long long s = sbase + (long long)(32 * i) * K;
        CP_ASYNC16(stb + AMATB + d, pBh + s);
    }
}

template <int OUTM>
__global__ void __launch_bounds__(256, 1)
gemm_mma(const __half* __restrict__ Ah, const __half* __restrict__ Bh,
         const float* __restrict__ bias, float outScale,
         float* __restrict__ C, __half* __restrict__ Ch,
         int N, int K, long long sA, long long sB, long long sC)
{
    extern __shared__ char sm[];
    const uint32_t sb = smem_u32(sm);
    const int tid = threadIdx.x;
    const int wid = tid >> 5;
    const int lane = tid & 31;
    const int wm = wid >> 2;          // 0..1
    const int wn = wid & 3;           // 0..3
    const long long m0 = blockIdx.y * BM;
    const long long n0 = blockIdx.x * BN;

    const __half* pAh = Ah + (long long)blockIdx.z * sA + m0 * K;
    const __half* pBh = Bh + (long long)blockIdx.z * sB + n0 * K;
    const long long zC = (long long)blockIdx.z * sC;

    const uint32_t lmo = (uint32_t)((lane & 15) * ROWB + (lane >> 4) * 16);

    float acc[4][8][4];
    #pragma unroll
    for (int i = 0; i < 4; i++)
        #pragma unroll
        for (int j = 0; j < 8; j++)
            #pragma unroll
            for (int q = 0; q < 4; q++) acc[i][j][q] = 0.0f;

    const int KT = K / BK;

    // prologue: stages 0..NST-2
    #pragma unroll
    for (int s = 0; s < NST - 1; s++) {
        produce_tile(sb + (uint32_t)s * STG, pAh + s * BK, pBh + s * BK, K, tid);
        CP_COMMIT();
    }

    for (int kt = 0; kt < KT; kt++) {
        cp_wait<NST - 2>();
        __syncthreads();

        const int nx = kt + NST - 1;
        if (nx < KT) {
            produce_tile(sb + (uint32_t)(nx % NST) * STG, pAh + nx * BK, pBh + nx * BK, K, tid);
        }
        CP_COMMIT();

        const uint32_t stb = sb + (uint32_t)(kt % NST) * STG;
        #pragma unroll
        for (int ks = 0; ks < 4; ks++) {
            const uint32_t kb = (uint32_t)(ks * 32);     // 16 halves * 2B
            uint32_t ah[4][4];
            #pragma unroll
            for (int mt = 0; mt < 4; mt++) {
                uint32_t rowb = (uint32_t)((wm * 64 + mt * 16) * ROWB);
                ldmx4(stb + rowb + lmo + kb, ah[mt]);
            }
            #pragma unroll
            for (int g = 0; g < 4; g++) {                // 16-col groups of warp's 64
                uint32_t rowb = (uint32_t)((wn * 64 + g * 16) * ROWB);
                uint32_t bh[4];
                ldmx4(stb + AMATB + rowb + lmo + kb, bh);
                #pragma unroll
                for (int mt = 0; mt < 4; mt++) {
                    #pragma unroll
                    for (int h = 0; h < 2; h++) {
                        mma16816(acc[mt][g * 2 + h], ah[mt], bh[h], bh[h + 2]);
                    }
                }
            }
        }
    }

    // epilogue
    const long long rb = m0 + wm * 64 + (lane >> 2);
    const long long cb = n0 + wn * 64 + (lane & 3) * 2;
    #pragma unroll
    for (int nt = 0; nt < 8; nt++) {
        const long long c = cb + nt * 8;
        float b0 = 0.0f, b1 = 0.0f;
        if (bias) { b0 = bias[c]; b1 = bias[c + 1]; }
        #pragma unroll
        for (int mt = 0; mt < 4; mt++) {
            const long long r = rb + mt * 16;
            float v00 = (acc[mt][nt][0] + b0) * outScale, v01 = (acc[mt][nt][1] + b1) * outScale;
            float v10 = (acc[mt][nt][2] + b0) * outScale, v11 = (acc[mt][nt][3] + b1) * outScale;
            if (OUTM == 0) {
                *(float2*)&C[zC + r * N + c]       = make_float2(v00, v01);
                *(float2*)&C[zC + (r + 8) * N + c] = make_float2(v10, v11);
            } else {
                *(__half2*)&Ch[zC + r * N + c] =
                    __halves2half2(__float2half_rn(v00), __float2half_rn(v01));
                *(__half2*)&Ch[zC + (r + 8) * N + c] =
                    __halves2half2(__float2half_rn(v10), __float2half_rn(v11));
            }
        }
    }
}

// ---------------------------------------------------------------------------
// fp32 -> fp16 round elementwise
// ---------------------------------------------------------------------------
__global__ void __launch_bounds__(256)
round_kernel(const float* __restrict__ src, __half* __restrict__ dst, long long n)
{
    long long i = ((long long)blockIdx.x * 256 + threadIdx.x) * 4;
    if (i >= n) return;
    float4 v = *(const float4*)(src + i);
    *(__half2*)(dst + i)     = __halves2half2(__float2half_rn(v.x), __float2half_rn(v.y));
    *(__half2*)(dst + i + 2) = __halves2half2(__float2half_rn(v.z), __float2half_rn(v.w));
}

// ---------------------------------------------------------------------------
// Row softmax: fp16 scaled logits in, fp32 math, fp16 probabilities out.
// 512 threads, warp-shuffle reductions.
// ---------------------------------------------------------------------------
__global__ void __launch_bounds__(512)
softmax_kernel(const __half* __restrict__ lg, __half* __restrict__ outP)
{
    __shared__ float buf[S_LEN];
    __shared__ float red[17];
    const long long row = blockIdx.x;
    const __half* p = lg + row * S_LEN;
    const int tid = threadIdx.x;
    const int wid = tid >> 5;
    const int lane = tid & 31;

    float mx = -1e30f;
    #pragma unroll
    for (int i = tid * 2; i < S_LEN; i += 1024) {
        __half2 hv = *(const __half2*)(p + i);
        float v0 = __low2float(hv), v1 = __high2float(hv);
        buf[i] = v0; buf[i + 1] = v1;
        mx = fmaxf(mx, fmaxf(v0, v1));
    }
    #pragma unroll
    for (int o = 16; o > 0; o >>= 1) mx = fmaxf(mx, __shfl_xor_sync(0xFFFFFFFFu, mx, o));
    if (lane == 0) red[wid] = mx;
    __syncthreads();
    if (tid == 0) {
        float m = red[0];
        #pragma unroll
        for (int i = 1; i < 16; i++) m = fmaxf(m, red[i]);
        red[16] = m;
    }
    __syncthreads();
    mx = red[16];

    float sum = 0.0f;
    #pragma unroll
    for (int i = tid; i < S_LEN; i += 512) {
        float e = __expf(buf[i] - mx);
        buf[i] = e;
        sum += e;
    }
    #pragma unroll
    for (int o = 16; o > 0; o >>= 1) sum += __shfl_xor_sync(0xFFFFFFFFu, sum, o);
    __syncthreads();
    if (lane == 0) red[wid] = sum;
    __syncthreads();
    if (tid == 0) {
        float s = 0.0f;
        #pragma unroll
        for (int i = 0; i < 16; i++) s += red[i];
        red[16] = s;
    }
    __syncthreads();
    const float inv = 1.0f / red[16];

    __half* op = outP + row * S_LEN;
    #pragma unroll
    for (int i = tid * 2; i < S_LEN; i += 1024) {
        *(__half2*)(op + i) = __halves2half2(__float2half_rn(buf[i] * inv),
                                             __float2half_rn(buf[i + 1] * inv));
    }
}

// ---------------------------------------------------------------------------
// Per-batch tiled transpose: half [R,C] -> half [C,R].
// ---------------------------------------------------------------------------
__global__ void __launch_bounds__(256)
transpose_hh_kernel(const __half* __restrict__ src, __half* __restrict__ dst, int R, int C)
{
    __shared__ __half t[32][34];
    const long long bofs = (long long)blockIdx.z * R * C;
    src += bofs; dst += bofs;
    int c0 = blockIdx.x * 32, r0 = blockIdx.y * 32;
    for (int i = threadIdx.y; i < 32; i += 8)
        t[i][threadIdx.x] = src[(long long)(r0 + i) * C + c0 + threadIdx.x];
    __syncthreads();
    for (int i = threadIdx.y; i < 32; i += 8)
        dst[(long long)(c0 + i) * R + r0 + threadIdx.x] = t[threadIdx.x][i];
}

// ---------------------------------------------------------------------------
extern "C" void kernel_launch(void* const* d_in, const int* in_sizes, int n_in,
                              void* d_out, int out_size)
{
    const float* x  = (const float*)d_in[0];
    const float* Wq = (const float*)d_in[1];
    const float* bq = (const float*)d_in[2];
    const float* Wk = (const float*)d_in[3];
    const float* bk = (const float*)d_in[4];
    const float* Wv = (const float*)d_in[5];
    const float* bv = (const float*)d_in[6];
    const float* Wc = (const float*)d_in[7];
    const float* bc = (const float*)d_in[8];
    float* out = (float*)d_out;

    __half *attLg, *attP, *xH, *QH, *KH, *VH, *VtH, *YH, *YpH;
    __half *WqH, *WkH, *WvH, *WcH;
    cudaGetSymbolAddress((void**)&attLg, g_attLg);
    cudaGetSymbolAddress((void**)&attP,  g_attP);
    cudaGetSymbolAddress((void**)&xH,    g_xH);
    cudaGetSymbolAddress((void**)&QH,    g_QH);
    cudaGetSymbolAddress((void**)&KH,    g_KH);
    cudaGetSymbolAddress((void**)&VH,    g_VH);
    cudaGetSymbolAddress((void**)&VtH,   g_VtH);
    cudaGetSymbolAddress((void**)&YH,    g_YH);
    cudaGetSymbolAddress((void**)&YpH,   g_YpH);
    cudaGetSymbolAddress((void**)&WqH,   g_WqH);
    cudaGetSymbolAddress((void**)&WkH,   g_WkH);
    cudaGetSymbolAddress((void**)&WvH,   g_WvH);
    cudaGetSymbolAddress((void**)&WcH,   g_WcH);

    cudaFuncSetAttribute(gemm_mma<0>, cudaFuncAttributeMaxDynamicSharedMemorySize, GSMEM);
    cudaFuncSetAttribute(gemm_mma<2>, cudaFuncAttributeMaxDynamicSharedMemorySize, GSMEM);

    const float scale = 0.03608439182435161f;   // 768^-0.5
    const long long sd = (long long)S_LEN * D_DIM;
    dim3 blk(256);
    dim3 tblk(32, 8);

    // ---- operand prep (single fp16 everywhere) ----
    round_kernel<<<(BSD / 4 + 255) / 256, blk>>>(x, xH, BSD);
    round_kernel<<<(DD / 4 + 255) / 256, blk>>>(Wq, WqH, DD);
    round_kernel<<<(DD / 4 + 255) / 256, blk>>>(Wk, WkH, DD);
    round_kernel<<<(DD / 4 + 255) / 256, blk>>>(Wv, WvH, DD);
    round_kernel<<<(DD / 4 + 255) / 256, blk>>>(Wc, WcH, DD);

    // ---- projections (1-term; Q carries the softmax scale) ----
    dim3 gp(D_DIM / BN, M_TOT / BM, 1);                  // (3,128,1)
    gemm_mma<2><<<gp, blk, GSMEM>>>(xH, WqH, bq, scale, nullptr, QH, D_DIM, D_DIM, 0, 0, 0);
    gemm_mma<2><<<gp, blk, GSMEM>>>(xH, WkH, bk, 1.0f,  nullptr, KH, D_DIM, D_DIM, 0, 0, 0);
    gemm_mma<2><<<gp, blk, GSMEM>>>(xH, WvH, bv, 1.0f,  nullptr, VH, D_DIM, D_DIM, 0, 0, 0);

    // ---- scaled logits[b] = (scale*Q[b]) @ K[b]^T ----
    dim3 ga(S_LEN / BN, S_LEN / BM, B_BATCH);            // (16,32,4)
    gemm_mma<2><<<ga, blk, GSMEM>>>(QH, KH, nullptr, 1.0f, nullptr, attLg,
                                    S_LEN, D_DIM, sd, sd, SSLL);

    // ---- softmax: fp16 logits -> fp16 probabilities ----
    softmax_kernel<<<M_TOT, 512>>>(attLg, attP);

    // ---- V^T per batch ----
    dim3 gt(D_DIM / 32, S_LEN / 32, B_BATCH);            // (24,128,4)
    transpose_hh_kernel<<<gt, tblk>>>(VH, VtH, S_LEN, D_DIM);

    // ---- Y[b] = att[b] @ Vt[b]^T (fp16 out) ----
    dim3 gy(D_DIM / BN, S_LEN / BM, B_BATCH);            // (3,32,4)
    gemm_mma<2><<<gy, blk, GSMEM>>>(attP, VtH, nullptr, 1.0f, nullptr, YH,
                                    D_DIM, S_LEN, SSLL, sd, sd);

    // ---- permutation (per-batch transpose) ----
    transpose_hh_kernel<<<gt, tblk>>>(YH, YpH, S_LEN, D_DIM);

    // ---- output projection -> d_out (fp32) ----
    gemm_mma<0><<<gp, blk, GSMEM>>>(YpH, WcH, bc, 1.0f, out, nullptr, D_DIM, D_DIM, 0, 0, 0);
}

// round 13
// speedup vs baseline: 2.7680x; 1.0195x over previous
#include <cuda_runtime.h>
#include <cuda_fp16.h>
#include <stdint.h>

// ---------------------------------------------------------------------------
// Problem constants
// ---------------------------------------------------------------------------
#define D_DIM 768
#define S_LEN 4096
#define B_BATCH 4
#define M_TOT (B_BATCH * S_LEN)            // 16384
#define BSD (B_BATCH * S_LEN * D_DIM)
#define SSLL ((long long)S_LEN * S_LEN)
#define ATT_N ((size_t)B_BATCH * S_LEN * S_LEN)
#define DD (D_DIM * D_DIM)

// ---------------------------------------------------------------------------
// Static device scratch (all fp16)
// ---------------------------------------------------------------------------
__device__ __align__(256) __half g_attLg[ATT_N];              // scaled fp16 logits
__device__ __align__(256) __half g_attP[ATT_N];               // fp16 probabilities
__device__ __align__(256) __half g_xH[BSD];
__device__ __align__(256) __half g_QH[BSD];                   // pre-scaled by 768^-0.5
__device__ __align__(256) __half g_KH[BSD];
__device__ __align__(256) __half g_VH[BSD];
__device__ __align__(256) __half g_VtH[BSD];
__device__ __align__(256) __half g_YH[BSD];
__device__ __align__(256) __half g_YpH[BSD];
__device__ __align__(256) __half g_WpackH[3 * DD];            // [Wq|Wk|Wv] as [2304,768]
__device__ __align__(256) float  g_bpack[3 * D_DIM];
__device__ __align__(256) __half g_WcH[DD];

// ---------------------------------------------------------------------------
// helpers
// ---------------------------------------------------------------------------
__device__ __forceinline__ uint32_t smem_u32(const void* p) {
    uint32_t a;
    asm("{ .reg .u64 t; cvta.to.shared.u64 t, %1; cvt.u32.u64 %0, t; }" : "=r"(a) : "l"(p));
    return a;
}
__device__ __forceinline__ void ldmx4(uint32_t addr, uint32_t* r) {
    asm volatile("ldmatrix.sync.aligned.m8n8.x4.shared.b16 {%0,%1,%2,%3}, [%4];"
                 : "=r"(r[0]), "=r"(r[1]), "=r"(r[2]), "=r"(r[3]) : "r"(addr));
}
__device__ __forceinline__ void mma16816(float* d, const uint32_t* a, uint32_t b0, uint32_t b1) {
    asm volatile("mma.sync.aligned.m16n8k16.row.col.f32.f16.f16.f32 "
                 "{%0,%1,%2,%3}, {%4,%5,%6,%7}, {%8,%9}, {%0,%1,%2,%3};"
                 : "+f"(d[0]), "+f"(d[1]), "+f"(d[2]), "+f"(d[3])
                 : "r"(a[0]), "r"(a[1]), "r"(a[2]), "r"(a[3]), "r"(b0), "r"(b1));
}
#define CP_ASYNC16(dst, src) \
    asm volatile("cp.async.cg.shared.global [%0], [%1], 16;" :: "r"(dst), "l"(src) : "memory")
#define CP_COMMIT() asm volatile("cp.async.commit_group;" ::: "memory")
template <int N>
__device__ __forceinline__ void cp_wait() {
    asm volatile("cp.async.wait_group %0;" :: "n"(N) : "memory");
}

#define ROWB 144

// ===========================================================================
// Big GEMM (QK^T): 128x256 tile, BK=64, 8 warps (2m x 4n), warp 64x64,
// 4-stage cp.async (216 KB smem), half output.
// ===========================================================================
#define BM 128
#define BN 256
#define BK 64
#define AMATB (128 * ROWB)          // 18432
#define BMATB (256 * ROWB)          // 36864
#define STG (AMATB + BMATB)         // 55296
#define NST 4
#define GSMEM (NST * STG)           // 221184

__device__ __forceinline__ void produce_tile(
    uint32_t stb, const __half* pAh, const __half* pBh, long long K, int tid)
{
    const int pr = tid >> 3;
    const int pc = tid & 7;
    const uint32_t dbase = (uint32_t)(pr * ROWB + pc * 16);
    const long long sbase = (long long)pr * K + pc * 8;
    #pragma unroll
    for (int i = 0; i < 4; i++) {
        CP_ASYNC16(stb + dbase + (uint32_t)(32 * i * ROWB), pAh + sbase + (long long)(32 * i) * K);
    }
    #pragma unroll
    for (int i = 0; i < 8; i++) {
        CP_ASYNC16(stb + AMATB + dbase + (uint32_t)(32 * i * ROWB),
                   pBh + sbase + (long long)(32 * i) * K);
    }
}

__global__ void __launch_bounds__(256, 1)
gemm_big(const __half* __restrict__ Ah, const __half* __restrict__ Bh,
         __half* __restrict__ Ch,
         int N, int K, long long sA, long long sB, long long sC)
{
    extern __shared__ char sm[];
    const uint32_t sb = smem_u32(sm);
    const int tid = threadIdx.x;
    const int wid = tid >> 5;
    const int lane = tid & 31;
    const int wm = wid >> 2;
    const int wn = wid & 3;
    const long long m0 = blockIdx.y * BM;
    const long long n0 = blockIdx.x * BN;

    const __half* pAh = Ah + (long long)blockIdx.z * sA + m0 * K;
    const __half* pBh = Bh + (long long)blockIdx.z * sB + n0 * K;
    const long long zC = (long long)blockIdx.z * sC;

    const uint32_t lmo = (uint32_t)((lane & 15) * ROWB + (lane >> 4) * 16);

    float acc[4][8][4];
    #pragma unroll
    for (int i = 0; i < 4; i++)
        #pragma unroll
        for (int j = 0; j < 8; j++)
            #pragma unroll
            for (int q = 0; q < 4; q++) acc[i][j][q] = 0.0f;

    const int KT = K / BK;
    #pragma unroll
    for (int s = 0; s < NST - 1; s++) {
        produce_tile(sb + (uint32_t)s * STG, pAh + s * BK, pBh + s * BK, K, tid);
        CP_COMMIT();
    }

    for (int kt = 0; kt < KT; kt++) {
        cp_wait<NST - 2>();
        __syncthreads();
        const int nx = kt + NST - 1;
        if (nx < KT)
            produce_tile(sb + (uint32_t)(nx % NST) * STG, pAh + nx * BK, pBh + nx * BK, K, tid);
        CP_COMMIT();

        const uint32_t stb = sb + (uint32_t)(kt % NST) * STG;
        #pragma unroll
        for (int ks = 0; ks < 4; ks++) {
            const uint32_t kb = (uint32_t)(ks * 32);
            uint32_t ah[4][4];
            #pragma unroll
            for (int mt = 0; mt < 4; mt++) {
                ldmx4(stb + (uint32_t)((wm * 64 + mt * 16) * ROWB) + lmo + kb, ah[mt]);
            }
            #pragma unroll
            for (int g = 0; g < 4; g++) {
                uint32_t bh[4];
                ldmx4(stb + AMATB + (uint32_t)((wn * 64 + g * 16) * ROWB) + lmo + kb, bh);
                #pragma unroll
                for (int mt = 0; mt < 4; mt++)
                    #pragma unroll
                    for (int h = 0; h < 2; h++)
                        mma16816(acc[mt][g * 2 + h], ah[mt], bh[h], bh[h + 2]);
            }
        }
    }

    const long long rb = m0 + wm * 64 + (lane >> 2);
    const long long cb = n0 + wn * 64 + (lane & 3) * 2;
    #pragma unroll
    for (int nt = 0; nt < 8; nt++) {
        const long long c = cb + nt * 8;
        #pragma unroll
        for (int mt = 0; mt < 4; mt++) {
            const long long r = rb + mt * 16;
            *(__half2*)&Ch[zC + r * N + c] =
                __halves2half2(__float2half_rn(acc[mt][nt][0]), __float2half_rn(acc[mt][nt][1]));
            *(__half2*)&Ch[zC + (r + 8) * N + c] =
                __halves2half2(__float2half_rn(acc[mt][nt][2]), __float2half_rn(acc[mt][nt][3]));
        }
    }
}

// ===========================================================================
// Small-N GEMM: 128x128 tile, BK=64, 8 warps (2m x 4n), warp 64x32,
// 3-stage cp.async (108 KB smem) -> 2 CTAs/SM.
// OUTM: 0 = fp32 C (+bias), 2 = half Ch, 3 = routed QKV (+packed bias, scale on Q)
// ===========================================================================
#define SBN 128
#define SBMATB (128 * ROWB)          // 18432
#define SSTG (2 * SBMATB)            // 36864
#define SNST 3
#define GSMEM_S (SNST * SSTG)        // 110592

__device__ __forceinline__ void produce_tile_s(
    uint32_t stb, const __half* pAh, const __half* pBh, long long K, int tid)
{
    const int pr = tid >> 3;
    const int pc = tid & 7;
    const uint32_t dbase = (uint32_t)(pr * ROWB + pc * 16);
    const long long sbase = (long long)pr * K + pc * 8;
    #pragma unroll
    for (int i = 0; i < 4; i++) {
        CP_ASYNC16(stb + dbase + (uint32_t)(32 * i * ROWB), pAh + sbase + (long long)(32 * i) * K);
        CP_ASYNC16(stb + SBMATB + dbase + (uint32_t)(32 * i * ROWB),
                   pBh + sbase + (long long)(32 * i) * K);
    }
}

template <int OUTM>
__global__ void __launch_bounds__(256, 2)
gemm_s(const __half* __restrict__ Ah, const __half* __restrict__ Bh,
       const float* __restrict__ bias, float qscale,
       float* __restrict__ C, __half* __restrict__ Ch,
       __half* __restrict__ O0, __half* __restrict__ O1, __half* __restrict__ O2,
       int N, int K, long long sA, long long sB, long long sC)
{
    extern __shared__ char sm[];
    const uint32_t sb = smem_u32(sm);
    const int tid = threadIdx.x;
    const int wid = tid >> 5;
    const int lane = tid & 31;
    const int wm = wid >> 2;          // 0..1
    const int wn = wid & 3;           // 0..3
    const long long m0 = blockIdx.y * BM;
    const long long n0 = blockIdx.x * SBN;

    const __half* pAh = Ah + (long long)blockIdx.z * sA + m0 * K;
    const __half* pBh = Bh + (long long)blockIdx.z * sB + n0 * K;
    const long long zC = (long long)blockIdx.z * sC;

    const uint32_t lmo = (uint32_t)((lane & 15) * ROWB + (lane >> 4) * 16);

    float acc[4][4][4];
    #pragma unroll
    for (int i = 0; i < 4; i++)
        #pragma unroll
        for (int j = 0; j < 4; j++)
            #pragma unroll
            for (int q = 0; q < 4; q++) acc[i][j][q] = 0.0f;

    const int KT = K / BK;
    #pragma unroll
    for (int s = 0; s < SNST - 1; s++) {
        produce_tile_s(sb + (uint32_t)s * SSTG, pAh + s * BK, pBh + s * BK, K, tid);
        CP_COMMIT();
    }

    for (int kt = 0; kt < KT; kt++) {
        cp_wait<SNST - 2>();
        __syncthreads();
        const int nx = kt + SNST - 1;
        if (nx < KT)
            produce_tile_s(sb + (uint32_t)(nx % SNST) * SSTG, pAh + nx * BK, pBh + nx * BK, K, tid);
        CP_COMMIT();

        const uint32_t stb = sb + (uint32_t)(kt % SNST) * SSTG;
        #pragma unroll
        for (int ks = 0; ks < 4; ks++) {
            const uint32_t kb = (uint32_t)(ks * 32);
            uint32_t ah[4][4];
            #pragma unroll
            for (int mt = 0; mt < 4; mt++) {
                ldmx4(stb + (uint32_t)((wm * 64 + mt * 16) * ROWB) + lmo + kb, ah[mt]);
            }
            #pragma unroll
            for (int g = 0; g < 2; g++) {
                uint32_t bh[4];
                ldmx4(stb + SBMATB + (uint32_t)((wn * 32 + g * 16) * ROWB) + lmo + kb, bh);
                #pragma unroll
                for (int mt = 0; mt < 4; mt++)
                    #pragma unroll
                    for (int h = 0; h < 2; h++)
                        mma16816(acc[mt][g * 2 + h], ah[mt], bh[h], bh[h + 2]);
            }
        }
    }

    // epilogue
    const long long rb = m0 + wm * 64 + (lane >> 2);
    const long long cb = n0 + wn * 32 + (lane & 3) * 2;

    // routing for OUTM==3 (per-CTA uniform: 768 % 128 == 0)
    int tgt = 0;
    __half* Orout = nullptr;
    float osc = 1.0f;
    if (OUTM == 3) {
        tgt = (int)(n0 >= 1536 ? 2 : (n0 >= 768 ? 1 : 0));
        Orout = (tgt == 0) ? O0 : ((tgt == 1) ? O1 : O2);
        osc = (tgt == 0) ? qscale : 1.0f;
    }

    #pragma unroll
    for (int nt = 0; nt < 4; nt++) {
        const long long c = cb + nt * 8;
        float b0 = 0.0f, b1 = 0.0f;
        if (OUTM == 0 || OUTM == 3) {
            if (bias) { b0 = bias[c]; b1 = bias[c + 1]; }
        }
        #pragma unroll
        for (int mt = 0; mt < 4; mt++) {
            const long long r = rb + mt * 16;
            float v00 = acc[mt][nt][0] + b0, v01 = acc[mt][nt][1] + b1;
            float v10 = acc[mt][nt][2] + b0, v11 = acc[mt][nt][3] + b1;
            if (OUTM == 0) {
                *(float2*)&C[zC + r * N + c]       = make_float2(v00, v01);
                *(float2*)&C[zC + (r + 8) * N + c] = make_float2(v10, v11);
            } else if (OUTM == 2) {
                *(__half2*)&Ch[zC + r * N + c] =
                    __halves2half2(__float2half_rn(v00), __float2half_rn(v01));
                *(__half2*)&Ch[zC + (r + 8) * N + c] =
                    __halves2half2(__float2half_rn(v10), __float2half_rn(v11));
            } else {
                const long long cl = c - (long long)tgt * D_DIM;
                *(__half2*)&Orout[r * D_DIM + cl] =
                    __halves2half2(__float2half_rn(v00 * osc), __float2half_rn(v01 * osc));
                *(__half2*)&Orout[(r + 8) * D_DIM + cl] =
                    __halves2half2(__float2half_rn(v10 * osc), __float2half_rn(v11 * osc));
            }
        }
    }
}

// ---------------------------------------------------------------------------
// fp32 -> fp16 round; QKV weight/bias pack
// ---------------------------------------------------------------------------
__global__ void __launch_bounds__(256)
round_kernel(const float* __restrict__ src, __half* __restrict__ dst, long long n)
{
    long long i = ((long long)blockIdx.x * 256 + threadIdx.x) * 4;
    if (i >= n) return;
    float4 v = *(const float4*)(src + i);
    *(__half2*)(dst + i)     = __halves2half2(__float2half_rn(v.x), __float2half_rn(v.y));
    *(__half2*)(dst + i + 2) = __halves2half2(__float2half_rn(v.z), __float2half_rn(v.w));
}

__global__ void __launch_bounds__(256)
pack_qkv_kernel(const float* __restrict__ Wq, const float* __restrict__ Wk,
                const float* __restrict__ Wv,
                const float* __restrict__ bq, const float* __restrict__ bk,
                const float* __restrict__ bv,
                __half* __restrict__ Wout, float* __restrict__ bout)
{
    long long i = ((long long)blockIdx.x * 256 + threadIdx.x) * 4;
    if (i < 3LL * DD) {
        int w = (int)(i / DD);
        long long j = i - (long long)w * DD;
        const float* src = (w == 0) ? Wq : ((w == 1) ? Wk : Wv);
        float4 v = *(const float4*)(src + j);
        *(__half2*)(Wout + i)     = __halves2half2(__float2half_rn(v.x), __float2half_rn(v.y));
        *(__half2*)(Wout + i + 2) = __halves2half2(__float2half_rn(v.z), __float2half_rn(v.w));
    }
    long long t = (long long)blockIdx.x * 256 + threadIdx.x;
    if (t < 3 * D_DIM) {
        int w = (int)(t / D_DIM);
        int j = (int)(t - w * D_DIM);
        const float* src = (w == 0) ? bq : ((w == 1) ? bk : bv);
        bout[t] = src[j];
    }
}

// ---------------------------------------------------------------------------
// Row softmax: fp16 scaled logits in, fp32 math, fp16 probabilities out.
// ---------------------------------------------------------------------------
__global__ void __launch_bounds__(512)
softmax_kernel(const __half* __restrict__ lg, __half* __restrict__ outP)
{
    __shared__ float buf[S_LEN];
    __shared__ float red[17];
    const long long row = blockIdx.x;
    const __half* p = lg + row * S_LEN;
    const int tid = threadIdx.x;
    const int wid = tid >> 5;
    const int lane = tid & 31;

    float mx = -1e30f;
    #pragma unroll
    for (int i = tid * 2; i < S_LEN; i += 1024) {
        __half2 hv = *(const __half2*)(p + i);
        float v0 = __low2float(hv), v1 = __high2float(hv);
        buf[i] = v0; buf[i + 1] = v1;
        mx = fmaxf(mx, fmaxf(v0, v1));
    }
    #pragma unroll
    for (int o = 16; o > 0; o >>= 1) mx = fmaxf(mx, __shfl_xor_sync(0xFFFFFFFFu, mx, o));
    if (lane == 0) red[wid] = mx;
    __syncthreads();
    if (tid == 0) {
        float m = red[0];
        #pragma unroll
        for (int i = 1; i < 16; i++) m = fmaxf(m, red[i]);
        red[16] = m;
    }
    __syncthreads();
    mx = red[16];

    float sum = 0.0f;
    #pragma unroll
    for (int i = tid; i < S_LEN; i += 512) {
        float e = __expf(buf[i] - mx);
        buf[i] = e;
        sum += e;
    }
    #pragma unroll
    for (int o = 16; o > 0; o >>= 1) sum += __shfl_xor_sync(0xFFFFFFFFu, sum, o);
    __syncthreads();
    if (lane == 0) red[wid] = sum;
    __syncthreads();
    if (tid == 0) {
        float s = 0.0f;
        #pragma unroll
        for (int i = 0; i < 16; i++) s += red[i];
        red[16] = s;
    }
    __syncthreads();
    const float inv = 1.0f / red[16];

    __half* op = outP + row * S_LEN;
    #pragma unroll
    for (int i = tid * 2; i < S_LEN; i += 1024) {
        *(__half2*)(op + i) = __halves2half2(__float2half_rn(buf[i] * inv),
                                             __float2half_rn(buf[i + 1] * inv));
    }
}

// ---------------------------------------------------------------------------
// Per-batch tiled transpose: half [R,C] -> half [C,R].
// ---------------------------------------------------------------------------
__global__ void __launch_bounds__(256)
transpose_hh_kernel(const __half* __restrict__ src, __half* __restrict__ dst, int R, int C)
{
    __shared__ __half t[32][34];
    const long long bofs = (long long)blockIdx.z * R * C;
    src += bofs; dst += bofs;
    int c0 = blockIdx.x * 32, r0 = blockIdx.y * 32;
    for (int i = threadIdx.y; i < 32; i += 8)
        t[i][threadIdx.x] = src[(long long)(r0 + i) * C + c0 + threadIdx.x];
    __syncthreads();
    for (int i = threadIdx.y; i < 32; i += 8)
        dst[(long long)(c0 + i) * R + r0 + threadIdx.x] = t[threadIdx.x][i];
}

// ---------------------------------------------------------------------------
extern "C" void kernel_launch(void* const* d_in, const int* in_sizes, int n_in,
                              void* d_out, int out_size)
{
    const float* x  = (const float*)d_in[0];
    const float* Wq = (const float*)d_in[1];
    const float* bq = (const float*)d_in[2];
    const float* Wk = (const float*)d_in[3];
    const float* bk = (const float*)d_in[4];
    const float* Wv = (const float*)d_in[5];
    const float* bv = (const float*)d_in[6];
    const float* Wc = (const float*)d_in[7];
    const float* bc = (const float*)d_in[8];
    float* out = (float*)d_out;

    __half *attLg, *attP, *xH, *QH, *KH, *VH, *VtH, *YH, *YpH, *WpackH, *WcH;
    float *bpack;
    cudaGetSymbolAddress((void**)&attLg,  g_attLg);
    cudaGetSymbolAddress((void**)&attP,   g_attP);
    cudaGetSymbolAddress((void**)&xH,     g_xH);
    cudaGetSymbolAddress((void**)&QH,     g_QH);
    cudaGetSymbolAddress((void**)&KH,     g_KH);
    cudaGetSymbolAddress((void**)&VH,     g_VH);
    cudaGetSymbolAddress((void**)&VtH,    g_VtH);
    cudaGetSymbolAddress((void**)&YH,     g_YH);
    cudaGetSymbolAddress((void**)&YpH,    g_YpH);
    cudaGetSymbolAddress((void**)&WpackH, g_WpackH);
    cudaGetSymbolAddress((void**)&bpack,  g_bpack);
    cudaGetSymbolAddress((void**)&WcH,    g_WcH);

    cudaFuncSetAttribute(gemm_big,  cudaFuncAttributeMaxDynamicSharedMemorySize, GSMEM);
    cudaFuncSetAttribute(gemm_s<0>, cudaFuncAttributeMaxDynamicSharedMemorySize, GSMEM_S);
    cudaFuncSetAttribute(gemm_s<2>, cudaFuncAttributeMaxDynamicSharedMemorySize, GSMEM_S);
    cudaFuncSetAttribute(gemm_s<3>, cudaFuncAttributeMaxDynamicSharedMemorySize, GSMEM_S);

    const float scale = 0.03608439182435161f;   // 768^-0.5
    const long long sd = (long long)S_LEN * D_DIM;
    dim3 blk(256);
    dim3 tblk(32, 8);

    // ---- operand prep ----
    round_kernel<<<(BSD / 4 + 255) / 256, blk>>>(x, xH, BSD);
    pack_qkv_kernel<<<(3 * DD / 4 + 255) / 256, blk>>>(Wq, Wk, Wv, bq, bk, bv, WpackH, bpack);
    round_kernel<<<(DD / 4 + 255) / 256, blk>>>(Wc, WcH, DD);

    // ---- fused QKV projection: [16384 x 2304] routed to QH/KH/VH ----
    dim3 gqkv(3 * D_DIM / SBN, M_TOT / BM, 1);           // (18,128,1)
    gemm_s<3><<<gqkv, blk, GSMEM_S>>>(xH, WpackH, bpack, scale,
                                      nullptr, nullptr, QH, KH, VH,
                                      3 * D_DIM, D_DIM, 0, 0, 0);

    // ---- scaled logits[b] = (scale*Q[b]) @ K[b]^T ----
    dim3 ga(S_LEN / BN, S_LEN / BM, B_BATCH);            // (16,32,4)
    gemm_big<<<ga, blk, GSMEM>>>(QH, KH, attLg, S_LEN, D_DIM, sd, sd, SSLL);

    // ---- softmax ----
    softmax_kernel<<<M_TOT, 512>>>(attLg, attP);

    // ---- V^T per batch ----
    dim3 gt(D_DIM / 32, S_LEN / 32, B_BATCH);            // (24,128,4)
    transpose_hh_kernel<<<gt, tblk>>>(VH, VtH, S_LEN, D_DIM);

    // ---- Y[b] = att[b] @ Vt[b]^T (half out, 2 CTAs/SM) ----
    dim3 gy(D_DIM / SBN, S_LEN / BM, B_BATCH);           // (6,32,4)
    gemm_s<2><<<gy, blk, GSMEM_S>>>(attP, VtH, nullptr, 1.0f,
                                    nullptr, YH, nullptr, nullptr, nullptr,
                                    D_DIM, S_LEN, SSLL, sd, sd);

    // ---- permutation (per-batch transpose) ----
    transpose_hh_kernel<<<gt, tblk>>>(YH, YpH, S_LEN, D_DIM);

    // ---- output projection -> d_out (fp32) ----
    dim3 gc(D_DIM / SBN, M_TOT / BM, 1);                 // (6,128,1)
    gemm_s<0><<<gc, blk, GSMEM_S>>>(YpH, WcH, bc, 1.0f,
                                    out, nullptr, nullptr, nullptr, nullptr,
                                    D_DIM, D_DIM, 0, 0, 0);
}

// round 14
// speedup vs baseline: 2.8460x; 1.0282x over previous
#include <cuda_runtime.h>
#include <cuda_fp16.h>
#include <stdint.h>

// ---------------------------------------------------------------------------
// Problem constants
// ---------------------------------------------------------------------------
#define D_DIM 768
#define S_LEN 4096
#define B_BATCH 4
#define M_TOT (B_BATCH * S_LEN)            // 16384
#define BSD (B_BATCH * S_LEN * D_DIM)
#define SSLL ((long long)S_LEN * S_LEN)
#define ATT_N ((size_t)B_BATCH * S_LEN * S_LEN)
#define DD (D_DIM * D_DIM)

// ---------------------------------------------------------------------------
// Static device scratch (all fp16)
// ---------------------------------------------------------------------------
__device__ __align__(256) __half g_attLg[ATT_N];              // scaled fp16 logits
__device__ __align__(256) __half g_attP[ATT_N];               // fp16 probabilities
__device__ __align__(256) __half g_xH[BSD];
__device__ __align__(256) __half g_QH[BSD];                   // pre-scaled by 768^-0.5
__device__ __align__(256) __half g_KH[BSD];
__device__ __align__(256) __half g_VH[BSD];
__device__ __align__(256) __half g_VtH[BSD];
__device__ __align__(256) __half g_YpH[BSD];                  // permuted attention output
__device__ __align__(256) __half g_WpackH[3 * DD];            // [Wq|Wk|Wv] as [2304,768]
__device__ __align__(256) float  g_bpack[3 * D_DIM];
__device__ __align__(256) __half g_WcH[DD];

// ---------------------------------------------------------------------------
// helpers
// ---------------------------------------------------------------------------
__device__ __forceinline__ uint32_t smem_u32(const void* p) {
    uint32_t a;
    asm("{ .reg .u64 t; cvta.to.shared.u64 t, %1; cvt.u32.u64 %0, t; }" : "=r"(a) : "l"(p));
    return a;
}
__device__ __forceinline__ void ldmx4(uint32_t addr, uint32_t* r) {
    asm volatile("ldmatrix.sync.aligned.m8n8.x4.shared.b16 {%0,%1,%2,%3}, [%4];"
                 : "=r"(r[0]), "=r"(r[1]), "=r"(r[2]), "=r"(r[3]) : "r"(addr));
}
__device__ __forceinline__ void mma16816(float* d, const uint32_t* a, uint32_t b0, uint32_t b1) {
    asm volatile("mma.sync.aligned.m16n8k16.row.col.f32.f16.f16.f32 "
                 "{%0,%1,%2,%3}, {%4,%5,%6,%7}, {%8,%9}, {%0,%1,%2,%3};"
                 : "+f"(d[0]), "+f"(d[1]), "+f"(d[2]), "+f"(d[3])
                 : "r"(a[0]), "r"(a[1]), "r"(a[2]), "r"(a[3]), "r"(b0), "r"(b1));
}
#define CP_ASYNC16(dst, src) \
    asm volatile("cp.async.cg.shared.global [%0], [%1], 16;" :: "r"(dst), "l"(src) : "memory")
#define CP_COMMIT() asm volatile("cp.async.commit_group;" ::: "memory")
template <int N>
__device__ __forceinline__ void cp_wait() {
    asm volatile("cp.async.wait_group %0;" :: "n"(N) : "memory");
}

#define ROWB 144

// ===========================================================================
// Big GEMM: 128x256 tile, BK=64, 8 warps (2m x 4n), warp 64x64,
// 4-stage cp.async (216 KB smem).
// OUTM: 2 = half C, 3 = routed QKV (+packed bias, scale on Q),
//       4 = transposed half out (writes Yp[d][s] per batch via smem transpose)
// ===========================================================================
#define BM 128
#define BN 256
#define BK 64
#define AMATB (128 * ROWB)          // 18432
#define BMATB (256 * ROWB)          // 36864
#define STG (AMATB + BMATB)         // 55296
#define NST 4
#define GSMEM (NST * STG)           // 221184
#define TSP 136                     // transpose-stage padded row (halves)

__device__ __forceinline__ void produce_tile(
    uint32_t stb, const __half* pAh, const __half* pBh, long long K, int tid)
{
    const int pr = tid >> 3;
    const int pc = tid & 7;
    const uint32_t dbase = (uint32_t)(pr * ROWB + pc * 16);
    const long long sbase = (long long)pr * K + pc * 8;
    #pragma unroll
    for (int i = 0; i < 4; i++) {
        CP_ASYNC16(stb + dbase + (uint32_t)(32 * i * ROWB), pAh + sbase + (long long)(32 * i) * K);
    }
    #pragma unroll
    for (int i = 0; i < 8; i++) {
        CP_ASYNC16(stb + AMATB + dbase + (uint32_t)(32 * i * ROWB),
                   pBh + sbase + (long long)(32 * i) * K);
    }
}

template <int OUTM>
__global__ void __launch_bounds__(256, 1)
gemm_big(const __half* __restrict__ Ah, const __half* __restrict__ Bh,
         const float* __restrict__ bias, float qscale,
         __half* __restrict__ Ch,
         __half* __restrict__ O0, __half* __restrict__ O1, __half* __restrict__ O2,
         int N, int K, long long sA, long long sB, long long sC)
{
    extern __shared__ char sm[];
    const uint32_t sb = smem_u32(sm);
    const int tid = threadIdx.x;
    const int wid = tid >> 5;
    const int lane = tid & 31;
    const int wm = wid >> 2;
    const int wn = wid & 3;
    const long long m0 = blockIdx.y * BM;
    const long long n0 = blockIdx.x * BN;

    const __half* pAh = Ah + (long long)blockIdx.z * sA + m0 * K;
    const __half* pBh = Bh + (long long)blockIdx.z * sB + n0 * K;
    const long long zC = (long long)blockIdx.z * sC;

    const uint32_t lmo = (uint32_t)((lane & 15) * ROWB + (lane >> 4) * 16);

    float acc[4][8][4];
    #pragma unroll
    for (int i = 0; i < 4; i++)
        #pragma unroll
        for (int j = 0; j < 8; j++)
            #pragma unroll
            for (int q = 0; q < 4; q++) acc[i][j][q] = 0.0f;

    const int KT = K / BK;
    #pragma unroll
    for (int s = 0; s < NST - 1; s++) {
        produce_tile(sb + (uint32_t)s * STG, pAh + s * BK, pBh + s * BK, K, tid);
        CP_COMMIT();
    }

    for (int kt = 0; kt < KT; kt++) {
        cp_wait<NST - 2>();
        __syncthreads();
        const int nx = kt + NST - 1;
        if (nx < KT)
            produce_tile(sb + (uint32_t)(nx % NST) * STG, pAh + nx * BK, pBh + nx * BK, K, tid);
        CP_COMMIT();

        const uint32_t stb = sb + (uint32_t)(kt % NST) * STG;
        #pragma unroll
        for (int ks = 0; ks < 4; ks++) {
            const uint32_t kb = (uint32_t)(ks * 32);
            uint32_t ah[4][4];
            #pragma unroll
            for (int mt = 0; mt < 4; mt++) {
                ldmx4(stb + (uint32_t)((wm * 64 + mt * 16) * ROWB) + lmo + kb, ah[mt]);
            }
            #pragma unroll
            for (int g = 0; g < 4; g++) {
                uint32_t bh[4];
                ldmx4(stb + AMATB + (uint32_t)((wn * 64 + g * 16) * ROWB) + lmo + kb, bh);
                #pragma unroll
                for (int mt = 0; mt < 4; mt++)
                    #pragma unroll
                    for (int h = 0; h < 2; h++)
                        mma16816(acc[mt][g * 2 + h], ah[mt], bh[h], bh[h + 2]);
            }
        }
    }

    const long long rb = m0 + wm * 64 + (lane >> 2);
    const long long cb = n0 + wn * 64 + (lane & 3) * 2;

    if (OUTM == 2) {
        #pragma unroll
        for (int nt = 0; nt < 8; nt++) {
            const long long c = cb + nt * 8;
            #pragma unroll
            for (int mt = 0; mt < 4; mt++) {
                const long long r = rb + mt * 16;
                *(__half2*)&Ch[zC + r * N + c] =
                    __halves2half2(__float2half_rn(acc[mt][nt][0]),
                                   __float2half_rn(acc[mt][nt][1]));
                *(__half2*)&Ch[zC + (r + 8) * N + c] =
                    __halves2half2(__float2half_rn(acc[mt][nt][2]),
                                   __float2half_rn(acc[mt][nt][3]));
            }
        }
    } else if (OUTM == 3) {
        // routed QKV: n0 multiple of 256, 768 % 256 == 0 -> whole tile one target
        const int tgt = (int)(n0 >= 1536 ? 2 : (n0 >= 768 ? 1 : 0));
        __half* Orout = (tgt == 0) ? O0 : ((tgt == 1) ? O1 : O2);
        const float osc = (tgt == 0) ? qscale : 1.0f;
        #pragma unroll
        for (int nt = 0; nt < 8; nt++) {
            const long long c = cb + nt * 8;
            const float b0 = bias[c], b1 = bias[c + 1];
            const long long cl = c - (long long)tgt * D_DIM;
            #pragma unroll
            for (int mt = 0; mt < 4; mt++) {
                const long long r = rb + mt * 16;
                float v00 = (acc[mt][nt][0] + b0) * osc, v01 = (acc[mt][nt][1] + b1) * osc;
                float v10 = (acc[mt][nt][2] + b0) * osc, v11 = (acc[mt][nt][3] + b1) * osc;
                *(__half2*)&Orout[r * D_DIM + cl] =
                    __halves2half2(__float2half_rn(v00), __float2half_rn(v01));
                *(__half2*)&Orout[(r + 8) * D_DIM + cl] =
                    __halves2half2(__float2half_rn(v10), __float2half_rn(v11));
            }
        }
    } else {
        // OUTM == 4: transposed write Yp[d][s] via smem (two 128x128 phases)
        cp_wait<0>();
        __syncthreads();
        __half* ts = (__half*)sm;                 // [128][TSP]
        const int rloc = wm * 64 + (lane >> 2);   // 0..127 row within tile
        #pragma unroll
        for (int ph = 0; ph < 2; ph++) {
            if ((wn >> 1) == ph) {
                const int clb = (wn & 1) * 64 + (lane & 3) * 2;
                #pragma unroll
                for (int nt = 0; nt < 8; nt++) {
                    const int cl = clb + nt * 8;
                    #pragma unroll
                    for (int mt = 0; mt < 4; mt++) {
                        const int r = rloc + mt * 16;
                        ts[cl * TSP + r]           = __float2half_rn(acc[mt][nt][0]);
                        ts[(cl + 1) * TSP + r]     = __float2half_rn(acc[mt][nt][1]);
                        ts[cl * TSP + r + 8]       = __float2half_rn(acc[mt][nt][2]);
                        ts[(cl + 1) * TSP + r + 8] = __float2half_rn(acc[mt][nt][3]);
                    }
                }
            }
            __syncthreads();
            {
                const int rowd = tid >> 1;
                const int base = (tid & 1) * 64;
                const long long d = n0 + ph * 128 + rowd;
                __half* dst = &Ch[zC + d * S_LEN + m0 + base];
                const __half* srcp = &ts[rowd * TSP + base];
                #pragma unroll
                for (int k = 0; k < 8; k++)
                    *(uint4*)(dst + k * 8) = *(const uint4*)(srcp + k * 8);
            }
            __syncthreads();
        }
    }
}

// ===========================================================================
// Small-N GEMM (Wc): 128x128 tile, 3-stage cp.async, 2 CTAs/SM, fp32 out+bias.
// ===========================================================================
#define SBN 128
#define SBMATB (128 * ROWB)          // 18432
#define SSTG (2 * SBMATB)            // 36864
#define SNST 3
#define GSMEM_S (SNST * SSTG)        // 110592

__device__ __forceinline__ void produce_tile_s(
    uint32_t stb, const __half* pAh, const __half* pBh, long long K, int tid)
{
    const int pr = tid >> 3;
    const int pc = tid & 7;
    const uint32_t dbase = (uint32_t)(pr * ROWB + pc * 16);
    const long long sbase = (long long)pr * K + pc * 8;
    #pragma unroll
    for (int i = 0; i < 4; i++) {
        CP_ASYNC16(stb + dbase + (uint32_t)(32 * i * ROWB), pAh + sbase + (long long)(32 * i) * K);
        CP_ASYNC16(stb + SBMATB + dbase + (uint32_t)(32 * i * ROWB),
                   pBh + sbase + (long long)(32 * i) * K);
    }
}

__global__ void __launch_bounds__(256, 2)
gemm_s(const __half* __restrict__ Ah, const __half* __restrict__ Bh,
       const float* __restrict__ bias, float* __restrict__ C,
       int N, int K)
{
    extern __shared__ char sm[];
    const uint32_t sb = smem_u32(sm);
    const int tid = threadIdx.x;
    const int wid = tid >> 5;
    const int lane = tid & 31;
    const int wm = wid >> 2;
    const int wn = wid & 3;
    const long long m0 = blockIdx.y * BM;
    const long long n0 = blockIdx.x * SBN;

    const __half* pAh = Ah + m0 * K;
    const __half* pBh = Bh + n0 * K;

    const uint32_t lmo = (uint32_t)((lane & 15) * ROWB + (lane >> 4) * 16);

    float acc[4][4][4];
    #pragma unroll
    for (int i = 0; i < 4; i++)
        #pragma unroll
        for (int j = 0; j < 4; j++)
            #pragma unroll
            for (int q = 0; q < 4; q++) acc[i][j][q] = 0.0f;

    const int KT = K / BK;
    #pragma unroll
    for (int s = 0; s < SNST - 1; s++) {
        produce_tile_s(sb + (uint32_t)s * SSTG, pAh + s * BK, pBh + s * BK, K, tid);
        CP_COMMIT();
    }

    for (int kt = 0; kt < KT; kt++) {
        cp_wait<SNST - 2>();
        __syncthreads();
        const int nx = kt + SNST - 1;
        if (nx < KT)
            produce_tile_s(sb + (uint32_t)(nx % SNST) * SSTG, pAh + nx * BK, pBh + nx * BK, K, tid);
        CP_COMMIT();

        const uint32_t stb = sb + (uint32_t)(kt % SNST) * SSTG;
        #pragma unroll
        for (int ks = 0; ks < 4; ks++) {
            const uint32_t kb = (uint32_t)(ks * 32);
            uint32_t ah[4][4];
            #pragma unroll
            for (int mt = 0; mt < 4; mt++) {
                ldmx4(stb + (uint32_t)((wm * 64 + mt * 16) * ROWB) + lmo + kb, ah[mt]);
            }
            #pragma unroll
            for (int g = 0; g < 2; g++) {
                uint32_t bh[4];
                ldmx4(stb + SBMATB + (uint32_t)((wn * 32 + g * 16) * ROWB) + lmo + kb, bh);
                #pragma unroll
                for (int mt = 0; mt < 4; mt++)
                    #pragma unroll
                    for (int h = 0; h < 2; h++)
                        mma16816(acc[mt][g * 2 + h], ah[mt], bh[h], bh[h + 2]);
            }
        }
    }

    const long long rb = m0 + wm * 64 + (lane >> 2);
    const long long cb = n0 + wn * 32 + (lane & 3) * 2;
    #pragma unroll
    for (int nt = 0; nt < 4; nt++) {
        const long long c = cb + nt * 8;
        const float b0 = bias[c], b1 = bias[c + 1];
        #pragma unroll
        for (int mt = 0; mt < 4; mt++) {
            const long long r = rb + mt * 16;
            *(float2*)&C[r * N + c] =
                make_float2(acc[mt][nt][0] + b0, acc[mt][nt][1] + b1);
            *(float2*)&C[(r + 8) * N + c] =
                make_float2(acc[mt][nt][2] + b0, acc[mt][nt][3] + b1);
        }
    }
}

// ---------------------------------------------------------------------------
// fp32 -> fp16 round; QKV weight/bias pack
// ---------------------------------------------------------------------------
__global__ void __launch_bounds__(256)
round_kernel(const float* __restrict__ src, __half* __restrict__ dst, long long n)
{
    long long i = ((long long)blockIdx.x * 256 + threadIdx.x) * 4;
    if (i >= n) return;
    float4 v = *(const float4*)(src + i);
    *(__half2*)(dst + i)     = __halves2half2(__float2half_rn(v.x), __float2half_rn(v.y));
    *(__half2*)(dst + i + 2) = __halves2half2(__float2half_rn(v.z), __float2half_rn(v.w));
}

__global__ void __launch_bounds__(256)
pack_qkv_kernel(const float* __restrict__ Wq, const float* __restrict__ Wk,
                const float* __restrict__ Wv,
                const float* __restrict__ bq, const float* __restrict__ bk,
                const float* __restrict__ bv,
                __half* __restrict__ Wout, float* __restrict__ bout)
{
    long long i = ((long long)blockIdx.x * 256 + threadIdx.x) * 4;
    if (i < 3LL * DD) {
        int w = (int)(i / DD);
        long long j = i - (long long)w * DD;
        const float* src = (w == 0) ? Wq : ((w == 1) ? Wk : Wv);
        float4 v = *(const float4*)(src + j);
        *(__half2*)(Wout + i)     = __halves2half2(__float2half_rn(v.x), __float2half_rn(v.y));
        *(__half2*)(Wout + i + 2) = __halves2half2(__float2half_rn(v.z), __float2half_rn(v.w));
    }
    long long t = (long long)blockIdx.x * 256 + threadIdx.x;
    if (t < 3 * D_DIM) {
        int w = (int)(t / D_DIM);
        int j = (int)(t - w * D_DIM);
        const float* src = (w == 0) ? bq : ((w == 1) ? bk : bv);
        bout[t] = src[j];
    }
}

// ---------------------------------------------------------------------------
// Row softmax: register-resident (8 values/thread), shuffle reductions.
// ---------------------------------------------------------------------------
__global__ void __launch_bounds__(512)
softmax_kernel(const __half* __restrict__ lg, __half* __restrict__ outP)
{
    __shared__ float red[17];
    const long long row = blockIdx.x;
    const __half* p = lg + row * S_LEN;
    const int tid = threadIdx.x;
    const int wid = tid >> 5;
    const int lane = tid & 31;

    float v[8];
    #pragma unroll
    for (int j = 0; j < 4; j++) {
        __half2 hv = *(const __half2*)(p + tid * 2 + j * 1024);
        v[2 * j]     = __low2float(hv);
        v[2 * j + 1] = __high2float(hv);
    }

    float mx = v[0];
    #pragma unroll
    for (int j = 1; j < 8; j++) mx = fmaxf(mx, v[j]);
    #pragma unroll
    for (int o = 16; o > 0; o >>= 1) mx = fmaxf(mx, __shfl_xor_sync(0xFFFFFFFFu, mx, o));
    if (lane == 0) red[wid] = mx;
    __syncthreads();
    if (tid == 0) {
        float m = red[0];
        #pragma unroll
        for (int i = 1; i < 16; i++) m = fmaxf(m, red[i]);
        red[16] = m;
    }
    __syncthreads();
    mx = red[16];

    float sum = 0.0f;
    #pragma unroll
    for (int j = 0; j < 8; j++) {
        v[j] = __expf(v[j] - mx);
        sum += v[j];
    }
    #pragma unroll
    for (int o = 16; o > 0; o >>= 1) sum += __shfl_xor_sync(0xFFFFFFFFu, sum, o);
    __syncthreads();
    if (lane == 0) red[wid] = sum;
    __syncthreads();
    if (tid == 0) {
        float s = 0.0f;
        #pragma unroll
        for (int i = 0; i < 16; i++) s += red[i];
        red[16] = s;
    }
    __syncthreads();
    const float inv = 1.0f / red[16];

    __half* op = outP + row * S_LEN;
    #pragma unroll
    for (int j = 0; j < 4; j++) {
        *(__half2*)(op + tid * 2 + j * 1024) =
            __halves2half2(__float2half_rn(v[2 * j] * inv),
                           __float2half_rn(v[2 * j + 1] * inv));
    }
}

// ---------------------------------------------------------------------------
// Per-batch tiled transpose: half [R,C] -> half [C,R]. (V only)
// ---------------------------------------------------------------------------
__global__ void __launch_bounds__(256)
transpose_hh_kernel(const __half* __restrict__ src, __half* __restrict__ dst, int R, int C)
{
    __shared__ __half t[32][34];
    const long long bofs = (long long)blockIdx.z * R * C;
    src += bofs; dst += bofs;
    int c0 = blockIdx.x * 32, r0 = blockIdx.y * 32;
    for (int i = threadIdx.y; i < 32; i += 8)
        t[i][threadIdx.x] = src[(long long)(r0 + i) * C + c0 + threadIdx.x];
    __syncthreads();
    for (int i = threadIdx.y; i < 32; i += 8)
        dst[(long long)(c0 + i) * R + r0 + threadIdx.x] = t[threadIdx.x][i];
}

// ---------------------------------------------------------------------------
extern "C" void kernel_launch(void* const* d_in, const int* in_sizes, int n_in,
                              void* d_out, int out_size)
{
    const float* x  = (const float*)d_in[0];
    const float* Wq = (const float*)d_in[1];
    const float* bq = (const float*)d_in[2];
    const float* Wk = (const float*)d_in[3];
    const float* bk = (const float*)d_in[4];
    const float* Wv = (const float*)d_in[5];
    const float* bv = (const float*)d_in[6];
    const float* Wc = (const float*)d_in[7];
    const float* bc = (const float*)d_in[8];
    float* out = (float*)d_out;

    __half *attLg, *attP, *xH, *QH, *KH, *VH, *VtH, *YpH, *WpackH, *WcH;
    float *bpack;
    cudaGetSymbolAddress((void**)&attLg,  g_attLg);
    cudaGetSymbolAddress((void**)&attP,   g_attP);
    cudaGetSymbolAddress((void**)&xH,     g_xH);
    cudaGetSymbolAddress((void**)&QH,     g_QH);
    cudaGetSymbolAddress((void**)&KH,     g_KH);
    cudaGetSymbolAddress((void**)&VH,     g_VH);
    cudaGetSymbolAddress((void**)&VtH,    g_VtH);
    cudaGetSymbolAddress((void**)&YpH,    g_YpH);
    cudaGetSymbolAddress((void**)&WpackH, g_WpackH);
    cudaGetSymbolAddress((void**)&bpack,  g_bpack);
    cudaGetSymbolAddress((void**)&WcH,    g_WcH);

    cudaFuncSetAttribute(gemm_big<2>, cudaFuncAttributeMaxDynamicSharedMemorySize, GSMEM);
    cudaFuncSetAttribute(gemm_big<3>, cudaFuncAttributeMaxDynamicSharedMemorySize, GSMEM);
    cudaFuncSetAttribute(gemm_big<4>, cudaFuncAttributeMaxDynamicSharedMemorySize, GSMEM);
    cudaFuncSetAttribute(gemm_s,      cudaFuncAttributeMaxDynamicSharedMemorySize, GSMEM_S);

    const float scale = 0.03608439182435161f;   // 768^-0.5
    const long long sd = (long long)S_LEN * D_DIM;
    dim3 blk(256);
    dim3 tblk(32, 8);

    // ---- operand prep ----
    round_kernel<<<(BSD / 4 + 255) / 256, blk>>>(x, xH, BSD);
    pack_qkv_kernel<<<(3 * DD / 4 + 255) / 256, blk>>>(Wq, Wk, Wv, bq, bk, bv, WpackH, bpack);
    round_kernel<<<(DD / 4 + 255) / 256, blk>>>(Wc, WcH, DD);

    // ---- fused QKV projection on big tile, routed to QH/KH/VH ----
    dim3 gqkv(3 * D_DIM / BN, M_TOT / BM, 1);            // (9,128,1)
    gemm_big<3><<<gqkv, blk, GSMEM>>>(xH, WpackH, bpack, scale,
                                      nullptr, QH, KH, VH,
                                      3 * D_DIM, D_DIM, 0, 0, 0);

    // ---- scaled logits[b] = (scale*Q[b]) @ K[b]^T ----
    dim3 ga(S_LEN / BN, S_LEN / BM, B_BATCH);            // (16,32,4)
    gemm_big<2><<<ga, blk, GSMEM>>>(QH, KH, nullptr, 1.0f, attLg,
                                    nullptr, nullptr, nullptr,
                                    S_LEN, D_DIM, sd, sd, SSLL);

    // ---- softmax ----
    softmax_kernel<<<M_TOT, 512>>>(attLg, attP);

    // ---- V^T per batch ----
    dim3 gt(D_DIM / 32, S_LEN / 32, B_BATCH);            // (24,128,4)
    transpose_hh_kernel<<<gt, tblk>>>(VH, VtH, S_LEN, D_DIM);

    // ---- Yp[b] = (att[b] @ Vt[b]^T)^T written directly (fused permutation) ----
    dim3 gy(D_DIM / BN, S_LEN / BM, B_BATCH);            // (3,32,4)
    gemm_big<4><<<gy, blk, GSMEM>>>(attP, VtH, nullptr, 1.0f, YpH,
                                    nullptr, nullptr, nullptr,
                                    D_DIM, S_LEN, SSLL, sd, sd);

    // ---- output projection -> d_out (fp32) ----
    dim3 gc(D_DIM / SBN, M_TOT / BM, 1);                 // (6,128,1)
    gemm_s<<<gc, blk, GSMEM_S>>>(YpH, WcH, bc, out, D_DIM, D_DIM);
}

// round 15
// speedup vs baseline: 2.8672x; 1.0075x over previous
#include <cuda_runtime.h>
#include <cuda_fp16.h>
#include <stdint.h>

// ---------------------------------------------------------------------------
// Problem constants
// ---------------------------------------------------------------------------
#define D_DIM 768
#define S_LEN 4096
#define B_BATCH 4
#define M_TOT (B_BATCH * S_LEN)            // 16384
#define BSD (B_BATCH * S_LEN * D_DIM)
#define SSLL ((long long)S_LEN * S_LEN)
#define ATT_N ((size_t)B_BATCH * S_LEN * S_LEN)
#define DD (D_DIM * D_DIM)
#define NTILES 16                          // QK^T n-tiles per row (4096/256)

// ---------------------------------------------------------------------------
// Static device scratch
// ---------------------------------------------------------------------------
__device__ __align__(256) __half g_attE[ATT_N];               // unnormalized exp(logits)
__device__ __align__(256) float  g_gpart[(size_t)M_TOT * NTILES]; // per-row partial sums
__device__ __align__(256) __half g_xH[BSD];
__device__ __align__(256) __half g_QH[BSD];                   // pre-scaled by 768^-0.5
__device__ __align__(256) __half g_KH[BSD];
__device__ __align__(256) __half g_VH[BSD];
__device__ __align__(256) __half g_VtH[BSD];
__device__ __align__(256) __half g_YpH[BSD];                  // permuted attention output
__device__ __align__(256) __half g_WpackH[3 * DD];            // [Wq|Wk|Wv] as [2304,768]
__device__ __align__(256) float  g_bpack[3 * D_DIM];
__device__ __align__(256) __half g_WcH[DD];

// ---------------------------------------------------------------------------
// helpers
// ---------------------------------------------------------------------------
__device__ __forceinline__ uint32_t smem_u32(const void* p) {
    uint32_t a;
    asm("{ .reg .u64 t; cvta.to.shared.u64 t, %1; cvt.u32.u64 %0, t; }" : "=r"(a) : "l"(p));
    return a;
}
__device__ __forceinline__ void ldmx4(uint32_t addr, uint32_t* r) {
    asm volatile("ldmatrix.sync.aligned.m8n8.x4.shared.b16 {%0,%1,%2,%3}, [%4];"
                 : "=r"(r[0]), "=r"(r[1]), "=r"(r[2]), "=r"(r[3]) : "r"(addr));
}
__device__ __forceinline__ void mma16816(float* d, const uint32_t* a, uint32_t b0, uint32_t b1) {
    asm volatile("mma.sync.aligned.m16n8k16.row.col.f32.f16.f16.f32 "
                 "{%0,%1,%2,%3}, {%4,%5,%6,%7}, {%8,%9}, {%0,%1,%2,%3};"
                 : "+f"(d[0]), "+f"(d[1]), "+f"(d[2]), "+f"(d[3])
                 : "r"(a[0]), "r"(a[1]), "r"(a[2]), "r"(a[3]), "r"(b0), "r"(b1));
}
#define CP_ASYNC16(dst, src) \
    asm volatile("cp.async.cg.shared.global [%0], [%1], 16;" :: "r"(dst), "l"(src) : "memory")
#define CP_COMMIT() asm volatile("cp.async.commit_group;" ::: "memory")
template <int N>
__device__ __forceinline__ void cp_wait() {
    asm volatile("cp.async.wait_group %0;" :: "n"(N) : "memory");
}

#define ROWB 144

// ===========================================================================
// Big GEMM: 128x256 tile, BK=64, 8 warps (2m x 4n), warp 64x64,
// 4-stage cp.async (216 KB smem).
// OUTM: 3 = routed QKV (+packed bias, scale on Q)
//       4 = att*V: transposed half out with 1/Z row scaling (fused permutation)
//       5 = QK^T: exp(acc) -> half Ch, per-row partial sums -> gpart
// ===========================================================================
#define BM 128
#define BN 256
#define BK 64
#define AMATB (128 * ROWB)          // 18432
#define BMATB (256 * ROWB)          // 36864
#define STG (AMATB + BMATB)         // 55296
#define NST 4
#define GSMEM (NST * STG)           // 221184
#define TSP 136                     // transpose-stage padded row (halves)

__device__ __forceinline__ void produce_tile(
    uint32_t stb, const __half* pAh, const __half* pBh, long long K, int tid)
{
    const int pr = tid >> 3;
    const int pc = tid & 7;
    const uint32_t dbase = (uint32_t)(pr * ROWB + pc * 16);
    const long long sbase = (long long)pr * K + pc * 8;
    #pragma unroll
    for (int i = 0; i < 4; i++) {
        CP_ASYNC16(stb + dbase + (uint32_t)(32 * i * ROWB), pAh + sbase + (long long)(32 * i) * K);
    }
    #pragma unroll
    for (int i = 0; i < 8; i++) {
        CP_ASYNC16(stb + AMATB + dbase + (uint32_t)(32 * i * ROWB),
                   pBh + sbase + (long long)(32 * i) * K);
    }
}

template <int OUTM>
__global__ void __launch_bounds__(256, 1)
gemm_big(const __half* __restrict__ Ah, const __half* __restrict__ Bh,
         const float* __restrict__ bias, float qscale,
         __half* __restrict__ Ch,
         __half* __restrict__ O0, __half* __restrict__ O1, __half* __restrict__ O2,
         float* __restrict__ gpw, const float* __restrict__ gpr,
         int N, int K, long long sA, long long sB, long long sC)
{
    extern __shared__ char sm[];
    const uint32_t sb = smem_u32(sm);
    const int tid = threadIdx.x;
    const int wid = tid >> 5;
    const int lane = tid & 31;
    const int wm = wid >> 2;
    const int wn = wid & 3;
    const long long m0 = blockIdx.y * BM;
    const long long n0 = blockIdx.x * BN;

    const __half* pAh = Ah + (long long)blockIdx.z * sA + m0 * K;
    const __half* pBh = Bh + (long long)blockIdx.z * sB + n0 * K;
    const long long zC = (long long)blockIdx.z * sC;

    const uint32_t lmo = (uint32_t)((lane & 15) * ROWB + (lane >> 4) * 16);

    float acc[4][8][4];
    #pragma unroll
    for (int i = 0; i < 4; i++)
        #pragma unroll
        for (int j = 0; j < 8; j++)
            #pragma unroll
            for (int q = 0; q < 4; q++) acc[i][j][q] = 0.0f;

    const int KT = K / BK;
    #pragma unroll
    for (int s = 0; s < NST - 1; s++) {
        produce_tile(sb + (uint32_t)s * STG, pAh + s * BK, pBh + s * BK, K, tid);
        CP_COMMIT();
    }

    for (int kt = 0; kt < KT; kt++) {
        cp_wait<NST - 2>();
        __syncthreads();
        const int nx = kt + NST - 1;
        if (nx < KT)
            produce_tile(sb + (uint32_t)(nx % NST) * STG, pAh + nx * BK, pBh + nx * BK, K, tid);
        CP_COMMIT();

        const uint32_t stb = sb + (uint32_t)(kt % NST) * STG;
        #pragma unroll
        for (int ks = 0; ks < 4; ks++) {
            const uint32_t kb = (uint32_t)(ks * 32);
            uint32_t ah[4][4];
            #pragma unroll
            for (int mt = 0; mt < 4; mt++) {
                ldmx4(stb + (uint32_t)((wm * 64 + mt * 16) * ROWB) + lmo + kb, ah[mt]);
            }
            #pragma unroll
            for (int g = 0; g < 4; g++) {
                uint32_t bh[4];
                ldmx4(stb + AMATB + (uint32_t)((wn * 64 + g * 16) * ROWB) + lmo + kb, bh);
                #pragma unroll
                for (int mt = 0; mt < 4; mt++)
                    #pragma unroll
                    for (int h = 0; h < 2; h++)
                        mma16816(acc[mt][g * 2 + h], ah[mt], bh[h], bh[h + 2]);
            }
        }
    }

    const long long rb = m0 + wm * 64 + (lane >> 2);
    const long long cb = n0 + wn * 64 + (lane & 3) * 2;

    if (OUTM == 3) {
        // routed QKV: n0 multiple of 256, 768 % 256 == 0 -> whole tile one target
        const int tgt = (int)(n0 >= 1536 ? 2 : (n0 >= 768 ? 1 : 0));
        __half* Orout = (tgt == 0) ? O0 : ((tgt == 1) ? O1 : O2);
        const float osc = (tgt == 0) ? qscale : 1.0f;
        #pragma unroll
        for (int nt = 0; nt < 8; nt++) {
            const long long c = cb + nt * 8;
            const float b0 = bias[c], b1 = bias[c + 1];
            const long long cl = c - (long long)tgt * D_DIM;
            #pragma unroll
            for (int mt = 0; mt < 4; mt++) {
                const long long r = rb + mt * 16;
                float v00 = (acc[mt][nt][0] + b0) * osc, v01 = (acc[mt][nt][1] + b1) * osc;
                float v10 = (acc[mt][nt][2] + b0) * osc, v11 = (acc[mt][nt][3] + b1) * osc;
                *(__half2*)&Orout[r * D_DIM + cl] =
                    __halves2half2(__float2half_rn(v00), __float2half_rn(v01));
                *(__half2*)&Orout[(r + 8) * D_DIM + cl] =
                    __halves2half2(__float2half_rn(v10), __float2half_rn(v11));
            }
        }
    } else if (OUTM == 5) {
        // QK^T: exp in-register, write unnormalized exps + per-row partial sums.
        float rs[8];                     // [mt*2 + half] row sums over this thread's cols
        #pragma unroll
        for (int i = 0; i < 8; i++) rs[i] = 0.0f;
        #pragma unroll
        for (int nt = 0; nt < 8; nt++) {
            const long long c = cb + nt * 8;
            #pragma unroll
            for (int mt = 0; mt < 4; mt++) {
                const long long r = rb + mt * 16;
                float e00 = __expf(acc[mt][nt][0]), e01 = __expf(acc[mt][nt][1]);
                float e10 = __expf(acc[mt][nt][2]), e11 = __expf(acc[mt][nt][3]);
                rs[mt * 2]     += e00 + e01;
                rs[mt * 2 + 1] += e10 + e11;
                *(__half2*)&Ch[zC + r * N + c] =
                    __halves2half2(__float2half_rn(e00), __float2half_rn(e01));
                *(__half2*)&Ch[zC + (r + 8) * N + c] =
                    __halves2half2(__float2half_rn(e10), __float2half_rn(e11));
            }
        }
        // quad reduce (lane&3 spans columns)
        #pragma unroll
        for (int i = 0; i < 8; i++) {
            rs[i] += __shfl_xor_sync(0xFFFFFFFFu, rs[i], 1);
            rs[i] += __shfl_xor_sync(0xFFFFFFFFu, rs[i], 2);
        }
        cp_wait<0>();
        __syncthreads();                                  // smem stages now free
        float* spart = (float*)sm;                        // [4][128]
        if ((lane & 3) == 0) {
            #pragma unroll
            for (int mt = 0; mt < 4; mt++) {
                #pragma unroll
                for (int h = 0; h < 2; h++) {
                    int rloc = wm * 64 + (lane >> 2) + mt * 16 + h * 8;
                    spart[wn * 128 + rloc] = rs[mt * 2 + h];
                }
            }
        }
        __syncthreads();
        if (tid < 128) {
            float s = spart[tid] + spart[128 + tid] + spart[256 + tid] + spart[384 + tid];
            gpw[((long long)blockIdx.z * S_LEN + m0 + tid) * NTILES + blockIdx.x] = s;
        }
    } else {
        // OUTM == 4: att*V. Row scales 1/Z, then transposed write Yp[d][s] via smem.
        float inv[4][2];
        #pragma unroll
        for (int mt = 0; mt < 4; mt++) {
            #pragma unroll
            for (int h = 0; h < 2; h++) {
                const long long gr = ((long long)blockIdx.z * S_LEN + rb + mt * 16 + h * 8);
                const float4* gp = (const float4*)&gpr[gr * NTILES];
                float4 a0 = gp[0], a1 = gp[1], a2 = gp[2], a3 = gp[3];
                float s = (a0.x + a0.y + a0.z + a0.w) + (a1.x + a1.y + a1.z + a1.w)
                        + (a2.x + a2.y + a2.z + a2.w) + (a3.x + a3.y + a3.z + a3.w);
                inv[mt][h] = 1.0f / s;
            }
        }
        cp_wait<0>();
        __syncthreads();
        __half* ts = (__half*)sm;                 // [128][TSP]
        const int rloc = wm * 64 + (lane >> 2);
        #pragma unroll
        for (int ph = 0; ph < 2; ph++) {
            if ((wn >> 1) == ph) {
                const int clb = (wn & 1) * 64 + (lane & 3) * 2;
                #pragma unroll
                for (int nt = 0; nt < 8; nt++) {
                    const int cl = clb + nt * 8;
                    #pragma unroll
                    for (int mt = 0; mt < 4; mt++) {
                        const int r = rloc + mt * 16;
                        ts[cl * TSP + r]           = __float2half_rn(acc[mt][nt][0] * inv[mt][0]);
                        ts[(cl + 1) * TSP + r]     = __float2half_rn(acc[mt][nt][1] * inv[mt][0]);
                        ts[cl * TSP + r + 8]       = __float2half_rn(acc[mt][nt][2] * inv[mt][1]);
                        ts[(cl + 1) * TSP + r + 8] = __float2half_rn(acc[mt][nt][3] * inv[mt][1]);
                    }
                }
            }
            __syncthreads();
            {
                const int rowd = tid >> 1;
                const int base = (tid & 1) * 64;
                const long long d = n0 + ph * 128 + rowd;
                __half* dst = &Ch[zC + d * S_LEN + m0 + base];
                const __half* srcp = &ts[rowd * TSP + base];
                #pragma unroll
                for (int k = 0; k < 8; k++)
                    *(uint4*)(dst + k * 8) = *(const uint4*)(srcp + k * 8);
            }
            __syncthreads();
        }
    }
}

// ===========================================================================
// Small-N GEMM (Wc): 128x128 tile, 3-stage cp.async, 2 CTAs/SM, fp32 out+bias.
// ===========================================================================
#define SBN 128
#define SBMATB (128 * ROWB)          // 18432
#define SSTG (2 * SBMATB)            // 36864
#define SNST 3
#define GSMEM_S (SNST * SSTG)        // 110592

__device__ __forceinline__ void produce_tile_s(
    uint32_t stb, const __half* pAh, const __half* pBh, long long K, int tid)
{
    const int pr = tid >> 3;
    const int pc = tid & 7;
    const uint32_t dbase = (uint32_t)(pr * ROWB + pc * 16);
    const long long sbase = (long long)pr * K + pc * 8;
    #pragma unroll
    for (int i = 0; i < 4; i++) {
        CP_ASYNC16(stb + dbase + (uint32_t)(32 * i * ROWB), pAh + sbase + (long long)(32 * i) * K);
        CP_ASYNC16(stb + SBMATB + dbase + (uint32_t)(32 * i * ROWB),
                   pBh + sbase + (long long)(32 * i) * K);
    }
}

__global__ void __launch_bounds__(256, 2)
gemm_s(const __half* __restrict__ Ah, const __half* __restrict__ Bh,
       const float* __restrict__ bias, float* __restrict__ C,
       int N, int K)
{
    extern __shared__ char sm[];
    const uint32_t sb = smem_u32(sm);
    const int tid = threadIdx.x;
    const int wid = tid >> 5;
    const int lane = tid & 31;
    const int wm = wid >> 2;
    const int wn = wid & 3;
    const long long m0 = blockIdx.y * BM;
    const long long n0 = blockIdx.x * SBN;

    const __half* pAh = Ah + m0 * K;
    const __half* pBh = Bh + n0 * K;

    const uint32_t lmo = (uint32_t)((lane & 15) * ROWB + (lane >> 4) * 16);

    float acc[4][4][4];
    #pragma unroll
    for (int i = 0; i < 4; i++)
        #pragma unroll
        for (int j = 0; j < 4; j++)
            #pragma unroll
            for (int q = 0; q < 4; q++) acc[i][j][q] = 0.0f;

    const int KT = K / BK;
    #pragma unroll
    for (int s = 0; s < SNST - 1; s++) {
        produce_tile_s(sb + (uint32_t)s * SSTG, pAh + s * BK, pBh + s * BK, K, tid);
        CP_COMMIT();
    }

    for (int kt = 0; kt < KT; kt++) {
        cp_wait<SNST - 2>();
        __syncthreads();
        const int nx = kt + SNST - 1;
        if (nx < KT)
            produce_tile_s(sb + (uint32_t)(nx % SNST) * SSTG, pAh + nx * BK, pBh + nx * BK, K, tid);
        CP_COMMIT();

        const uint32_t stb = sb + (uint32_t)(kt % SNST) * SSTG;
        #pragma unroll
        for (int ks = 0; ks < 4; ks++) {
            const uint32_t kb = (uint32_t)(ks * 32);
            uint32_t ah[4][4];
            #pragma unroll
            for (int mt = 0; mt < 4; mt++) {
                ldmx4(stb + (uint32_t)((wm * 64 + mt * 16) * ROWB) + lmo + kb, ah[mt]);
            }
            #pragma unroll
            for (int g = 0; g < 2; g++) {
                uint32_t bh[4];
                ldmx4(stb + SBMATB + (uint32_t)((wn * 32 + g * 16) * ROWB) + lmo + kb, bh);
                #pragma unroll
                for (int mt = 0; mt < 4; mt++)
                    #pragma unroll
                    for (int h = 0; h < 2; h++)
                        mma16816(acc[mt][g * 2 + h], ah[mt], bh[h], bh[h + 2]);
            }
        }
    }

    const long long rb = m0 + wm * 64 + (lane >> 2);
    const long long cb = n0 + wn * 32 + (lane & 3) * 2;
    #pragma unroll
    for (int nt = 0; nt < 4; nt++) {
        const long long c = cb + nt * 8;
        const float b0 = bias[c], b1 = bias[c + 1];
        #pragma unroll
        for (int mt = 0; mt < 4; mt++) {
            const long long r = rb + mt * 16;
            *(float2*)&C[r * N + c] =
                make_float2(acc[mt][nt][0] + b0, acc[mt][nt][1] + b1);
            *(float2*)&C[(r + 8) * N + c] =
                make_float2(acc[mt][nt][2] + b0, acc[mt][nt][3] + b1);
        }
    }
}

// ---------------------------------------------------------------------------
// Merged prep: x round + QKV weight/bias pack + Wc round (blockIdx-partitioned)
// ---------------------------------------------------------------------------
#define NB_X  (BSD / 4 / 256)                 // 12288
#define NB_WP (3 * DD / 4 / 256)              // 1728
#define NB_WC (DD / 4 / 256)                  // 576
#define NB_PREP (NB_X + NB_WP + NB_WC)

__global__ void __launch_bounds__(256)
prep_kernel(const float* __restrict__ x,
            const float* __restrict__ Wq, const float* __restrict__ Wk,
            const float* __restrict__ Wv, const float* __restrict__ Wc,
            const float* __restrict__ bq, const float* __restrict__ bk,
            const float* __restrict__ bv,
            __half* __restrict__ xH, __half* __restrict__ Wpack,
            __half* __restrict__ WcH, float* __restrict__ bpack)
{
    const int b = blockIdx.x;
    if (b < NB_X) {
        long long i = ((long long)b * 256 + threadIdx.x) * 4;
        float4 v = *(const float4*)(x + i);
        *(__half2*)(xH + i)     = __halves2half2(__float2half_rn(v.x), __float2half_rn(v.y));
        *(__half2*)(xH + i + 2) = __halves2half2(__float2half_rn(v.z), __float2half_rn(v.w));
    } else if (b < NB_X + NB_WP) {
        long long i = ((long long)(b - NB_X) * 256 + threadIdx.x) * 4;
        int w = (int)(i / DD);
        long long j = i - (long long)w * DD;
        const float* src = (w == 0) ? Wq : ((w == 1) ? Wk : Wv);
        float4 v = *(const float4*)(src + j);
        *(__half2*)(Wpack + i)     = __halves2half2(__float2half_rn(v.x), __float2half_rn(v.y));
        *(__half2*)(Wpack + i + 2) = __halves2half2(__float2half_rn(v.z), __float2half_rn(v.w));
        long long t = (long long)(b - NB_X) * 256 + threadIdx.x;
        if (t < 3 * D_DIM) {
            int bw = (int)(t / D_DIM);
            int bj = (int)(t - bw * D_DIM);
            const float* bsrc = (bw == 0) ? bq : ((bw == 1) ? bk : bv);
            bpack[t] = bsrc[bj];
        }
    } else {
        long long i = ((long long)(b - NB_X - NB_WP) * 256 + threadIdx.x) * 4;
        float4 v = *(const float4*)(Wc + i);
        *(__half2*)(WcH + i)     = __halves2half2(__float2half_rn(v.x), __float2half_rn(v.y));
        *(__half2*)(WcH + i + 2) = __halves2half2(__float2half_rn(v.z), __float2half_rn(v.w));
    }
}

// ---------------------------------------------------------------------------
// Per-batch tiled transpose: half [R,C] -> half [C,R]. (V only)
// ---------------------------------------------------------------------------
__global__ void __launch_bounds__(256)
transpose_hh_kernel(const __half* __restrict__ src, __half* __restrict__ dst, int R, int C)
{
    __shared__ __half t[32][34];
    const long long bofs = (long long)blockIdx.z * R * C;
    src += bofs; dst += bofs;
    int c0 = blockIdx.x * 32, r0 = blockIdx.y * 32;
    for (int i = threadIdx.y; i < 32; i += 8)
        t[i][threadIdx.x] = src[(long long)(r0 + i) * C + c0 + threadIdx.x];
    __syncthreads();
    for (int i = threadIdx.y; i < 32; i += 8)
        dst[(long long)(c0 + i) * R + r0 + threadIdx.x] = t[threadIdx.x][i];
}

// ---------------------------------------------------------------------------
extern "C" void kernel_launch(void* const* d_in, const int* in_sizes, int n_in,
                              void* d_out, int out_size)
{
    const float* x  = (const float*)d_in[0];
    const float* Wq = (const float*)d_in[1];
    const float* bq = (const float*)d_in[2];
    const float* Wk = (const float*)d_in[3];
    const float* bk = (const float*)d_in[4];
    const float* Wv = (const float*)d_in[5];
    const float* bv = (const float*)d_in[6];
    const float* Wc = (const float*)d_in[7];
    const float* bc = (const float*)d_in[8];
    float* out = (float*)d_out;

    __half *attE, *xH, *QH, *KH, *VH, *VtH, *YpH, *WpackH, *WcH;
    float *bpack, *gpart;
    cudaGetSymbolAddress((void**)&attE,   g_attE);
    cudaGetSymbolAddress((void**)&gpart,  g_gpart);
    cudaGetSymbolAddress((void**)&xH,     g_xH);
    cudaGetSymbolAddress((void**)&QH,     g_QH);
    cudaGetSymbolAddress((void**)&KH,     g_KH);
    cudaGetSymbolAddress((void**)&VH,     g_VH);
    cudaGetSymbolAddress((void**)&VtH,    g_VtH);
    cudaGetSymbolAddress((void**)&YpH,    g_YpH);
    cudaGetSymbolAddress((void**)&WpackH, g_WpackH);
    cudaGetSymbolAddress((void**)&bpack,  g_bpack);
    cudaGetSymbolAddress((void**)&WcH,    g_WcH);

    cudaFuncSetAttribute(gemm_big<3>, cudaFuncAttributeMaxDynamicSharedMemorySize, GSMEM);
    cudaFuncSetAttribute(gemm_big<4>, cudaFuncAttributeMaxDynamicSharedMemorySize, GSMEM);
    cudaFuncSetAttribute(gemm_big<5>, cudaFuncAttributeMaxDynamicSharedMemorySize, GSMEM);
    cudaFuncSetAttribute(gemm_s,      cudaFuncAttributeMaxDynamicSharedMemorySize, GSMEM_S);

    const float scale = 0.03608439182435161f;   // 768^-0.5
    const long long sd = (long long)S_LEN * D_DIM;
    dim3 blk(256);
    dim3 tblk(32, 8);

    // ---- merged operand prep ----
    prep_kernel<<<NB_PREP, blk>>>(x, Wq, Wk, Wv, Wc, bq, bk, bv,
                                  xH, WpackH, WcH, bpack);

    // ---- fused QKV projection on big tile, routed to QH/KH/VH ----
    dim3 gqkv(3 * D_DIM / BN, M_TOT / BM, 1);            // (9,128,1)
    gemm_big<3><<<gqkv, blk, GSMEM>>>(xH, WpackH, bpack, scale,
                                      nullptr, QH, KH, VH, nullptr, nullptr,
                                      3 * D_DIM, D_DIM, 0, 0, 0);

    // ---- attE[b] = exp((scale*Q[b]) @ K[b]^T) + row partial sums ----
    dim3 ga(S_LEN / BN, S_LEN / BM, B_BATCH);            // (16,32,4)
    gemm_big<5><<<ga, blk, GSMEM>>>(QH, KH, nullptr, 1.0f, attE,
                                    nullptr, nullptr, nullptr, gpart, nullptr,
                                    S_LEN, D_DIM, sd, sd, SSLL);

    // ---- V^T per batch ----
    dim3 gt(D_DIM / 32, S_LEN / 32, B_BATCH);            // (24,128,4)
    transpose_hh_kernel<<<gt, tblk>>>(VH, VtH, S_LEN, D_DIM);

    // ---- Yp[b] = ((attE[b]/Z) @ Vt[b]^T)^T written directly ----
    dim3 gy(D_DIM / BN, S_LEN / BM, B_BATCH);            // (3,32,4)
    gemm_big<4><<<gy, blk, GSMEM>>>(attE, VtH, nullptr, 1.0f, YpH,
                                    nullptr, nullptr, nullptr, nullptr, gpart,
                                    D_DIM, S_LEN, SSLL, sd, sd);

    // ---- output projection -> d_out (fp32) ----
    dim3 gc(D_DIM / SBN, M_TOT / BM, 1);                 // (6,128,1)
    gemm_s<<<gc, blk, GSMEM_S>>>(YpH, WcH, bc, out, D_DIM, D_DIM);
}